// round 4
// baseline (speedup 1.0000x reference)
#include <cuda_runtime.h>

#define EPSI 1e-7f

// ---------------------------------------------------------------------------
// Scratch (B*nh*W*H*d = 4*8*128*128*64 = 33,554,432 floats = 128 MiB each).
// Q,K,V stored as [B][nh][W][H][d]; XV stored as [B][nh][H][W][d].
// ---------------------------------------------------------------------------
__device__ float g_Q[33554432];
__device__ float g_K[33554432];
__device__ float g_V[33554432];
__device__ float g_XV[33554432];

// ---------------------------------------------------------------------------
// Projection GEMM: out[pix][f] = sum_c x[pix][c] * W[c][f] + bias[f]
// M=65536, N=512, K=512.  BM=BN=64, BK=16, 256 threads, 4x4 micro-tile.
// blockIdx.z selects which projection (0=Q, 1=K, 2=V).
// Output written directly into the [B][nh][W][H][d] layout.
// ---------------------------------------------------------------------------
__global__ void __launch_bounds__(256) proj_kernel(
    const float* __restrict__ x,
    const float* __restrict__ wq, const float* __restrict__ bq,
    const float* __restrict__ wk, const float* __restrict__ bk,
    const float* __restrict__ wv, const float* __restrict__ bv)
{
    __shared__ float As[16][65];   // [k][m], padded
    __shared__ float Bs[16][64];   // [k][f]

    const int which = blockIdx.z;
    const float* __restrict__ Wm   = (which == 0) ? wq : (which == 1) ? wk : wv;
    const float* __restrict__ bias = (which == 0) ? bq : (which == 1) ? bk : bv;
    float* __restrict__ outp       = (which == 0) ? g_Q : (which == 1) ? g_K : g_V;

    const int tid = threadIdx.x;
    const int tx  = tid & 15;
    const int ty  = tid >> 4;
    const int m0  = blockIdx.x * 64;   // pixel tile
    const int n0  = blockIdx.y * 64;   // channel (f) tile: exactly one head

    // A-tile load mapping: thread -> (row m, 4 consecutive k)
    const int am = tid >> 2;
    const int ak = (tid & 3) * 4;
    // B-tile load mapping: thread -> (row k, 4 consecutive f)
    const int bkr = tid >> 4;
    const int bfc = (tid & 15) * 4;

    float acc[4][4] = {};

    for (int k0 = 0; k0 < 512; k0 += 16) {
        float4 a4 = *(const float4*)(x + (m0 + am) * 512 + k0 + ak);
        As[ak + 0][am] = a4.x;
        As[ak + 1][am] = a4.y;
        As[ak + 2][am] = a4.z;
        As[ak + 3][am] = a4.w;
        *(float4*)(&Bs[bkr][bfc]) = *(const float4*)(Wm + (k0 + bkr) * 512 + n0 + bfc);
        __syncthreads();
#pragma unroll
        for (int kk = 0; kk < 16; kk++) {
            float a0 = As[kk][ty * 4 + 0];
            float a1 = As[kk][ty * 4 + 1];
            float a2 = As[kk][ty * 4 + 2];
            float a3 = As[kk][ty * 4 + 3];
            float4 b4 = *(const float4*)(&Bs[kk][tx * 4]);
            acc[0][0] += a0 * b4.x; acc[0][1] += a0 * b4.y; acc[0][2] += a0 * b4.z; acc[0][3] += a0 * b4.w;
            acc[1][0] += a1 * b4.x; acc[1][1] += a1 * b4.y; acc[1][2] += a1 * b4.z; acc[1][3] += a1 * b4.w;
            acc[2][0] += a2 * b4.x; acc[2][1] += a2 * b4.y; acc[2][2] += a2 * b4.z; acc[2][3] += a2 * b4.w;
            acc[3][0] += a3 * b4.x; acc[3][1] += a3 * b4.y; acc[3][2] += a3 * b4.z; acc[3][3] += a3 * b4.w;
        }
        __syncthreads();
    }

    // Epilogue: bias + scatter into [B][nh][W][H][d]
    const int n  = n0 >> 6;        // head index (BN=64 == d, so one head per CTA)
    const int dd = tx * 4;
    float4 bb;
    bb.x = bias[n0 + dd + 0];
    bb.y = bias[n0 + dd + 1];
    bb.z = bias[n0 + dd + 2];
    bb.w = bias[n0 + dd + 3];
#pragma unroll
    for (int i = 0; i < 4; i++) {
        const int pix = m0 + ty * 4 + i;
        const int b = pix >> 14;
        const int h = (pix >> 7) & 127;
        const int w = pix & 127;
        const int base = (((b * 8 + n) * 128 + w) * 128 + h) * 64;
        float4 o;
        o.x = acc[i][0] + bb.x;
        o.y = acc[i][1] + bb.y;
        o.z = acc[i][2] + bb.z;
        o.w = acc[i][3] + bb.w;
        *(float4*)(outp + base + dd) = o;
    }
}

// ---------------------------------------------------------------------------
// Axial attention, one CTA per (b, head, line).
//   stage 1 (columns): line = w.  Q/K/V blocks contiguous in [B][nh][W][H][d].
//                      Output -> g_XV in [B][nh][H][W][d].
//   stage 2 (rows):    line = h.  Q/K rows strided (8192 floats), XV block
//                      contiguous.  Output -> d_out [B,H,W,512], c = d*8 + n.
// 256 threads; S computed with 8x8 micro-tiles; softmax per row by warps;
// O = S*V with 8x4 micro-tiles.
// ---------------------------------------------------------------------------
__global__ void __launch_bounds__(256) attn_kernel(float* __restrict__ out, const int stage)
{
    extern __shared__ float smem[];
    float* S   = smem;            // 128*128 = 16384
    float* Qs  = smem + 16384;    // 128*64  =  8192  ([row][d])
    float* KsT = smem + 24576;    // 64*132  =  8448  ([d][row], padded)
    float* Vs  = smem + 33024;    // 128*64  =  8192  ([row][d])

    const int tid = threadIdx.x;
    const int x_  = blockIdx.x;                    // w (stage1) or h (stage2)
    const int b8n = blockIdx.z * 8 + blockIdx.y;   // b*8 + n

    const float* __restrict__ Qg = g_Q;
    const float* __restrict__ Kg = g_K;
    const float* __restrict__ Vg = (stage == 1) ? g_V : g_XV;

    int qbase, rstride, vbase;
    if (stage == 1) {
        qbase   = (b8n * 128 + x_) * 8192;
        rstride = 64;
        vbase   = qbase;
    } else {
        qbase   = b8n * 1048576 + x_ * 64;
        rstride = 8192;
        vbase   = (b8n * 128 + x_) * 8192;
    }

    // ---- load Q (natural), K (transposed), V (natural) ----
    for (int idx = tid; idx < 2048; idx += 256) {
        const int dd4 = (idx & 15) * 4;
        const int row = idx >> 4;
        const int goff = qbase + row * rstride + dd4;
        float4 q4 = *(const float4*)(Qg + goff);
        *(float4*)(Qs + row * 64 + dd4) = q4;
        float4 k4 = *(const float4*)(Kg + goff);
        KsT[(dd4 + 0) * 132 + row] = k4.x;
        KsT[(dd4 + 1) * 132 + row] = k4.y;
        KsT[(dd4 + 2) * 132 + row] = k4.z;
        KsT[(dd4 + 3) * 132 + row] = k4.w;
        *(float4*)(Vs + idx * 4) = *(const float4*)(Vg + vbase + idx * 4);
    }
    __syncthreads();

    // ---- S = Q * K^T, clip(+-(1-eps)), * 1/8 ----
    const int tx = tid & 15, ty = tid >> 4;
    const int ri = ty * 8, cj = tx * 8;
    {
        float acc[8][8] = {};
#pragma unroll 8
        for (int kk = 0; kk < 64; kk++) {
            float a[8];
#pragma unroll
            for (int i = 0; i < 8; i++) a[i] = Qs[(ri + i) * 64 + kk];
            float4 b0 = *(const float4*)(KsT + kk * 132 + cj);
            float4 b1 = *(const float4*)(KsT + kk * 132 + cj + 4);
            float bb[8] = { b0.x, b0.y, b0.z, b0.w, b1.x, b1.y, b1.z, b1.w };
#pragma unroll
            for (int i = 0; i < 8; i++)
#pragma unroll
                for (int j = 0; j < 8; j++)
                    acc[i][j] += a[i] * bb[j];
        }
        const float lo = -1.0f + EPSI, hi = 1.0f - EPSI;
#pragma unroll
        for (int i = 0; i < 8; i++) {
#pragma unroll
            for (int j = 0; j < 8; j++) {
                S[(ri + i) * 128 + cj + j] =
                    fminf(fmaxf(acc[i][j], lo), hi) * 0.125f;
            }
        }
    }
    __syncthreads();

    // ---- row-wise softmax (fp32), clip [eps, 1-eps] ----
    {
        const int wid = tid >> 5, lane = tid & 31;
        for (int rr = 0; rr < 16; rr++) {
            float* srow = S + (wid * 16 + rr) * 128;
            float v0 = srow[lane];
            float v1 = srow[lane + 32];
            float v2 = srow[lane + 64];
            float v3 = srow[lane + 96];
            float mx = fmaxf(fmaxf(v0, v1), fmaxf(v2, v3));
#pragma unroll
            for (int off = 16; off; off >>= 1)
                mx = fmaxf(mx, __shfl_xor_sync(0xffffffffu, mx, off));
            float e0 = __expf(v0 - mx);
            float e1 = __expf(v1 - mx);
            float e2 = __expf(v2 - mx);
            float e3 = __expf(v3 - mx);
            float s = e0 + e1 + e2 + e3;
#pragma unroll
            for (int off = 16; off; off >>= 1)
                s += __shfl_xor_sync(0xffffffffu, s, off);
            const float inv = 1.0f / s;
            const float alo = EPSI, ahi = 1.0f - EPSI;
            srow[lane]      = fminf(fmaxf(e0 * inv, alo), ahi);
            srow[lane + 32] = fminf(fmaxf(e1 * inv, alo), ahi);
            srow[lane + 64] = fminf(fmaxf(e2 * inv, alo), ahi);
            srow[lane + 96] = fminf(fmaxf(e3 * inv, alo), ahi);
        }
    }
    __syncthreads();

    // ---- O = S * V  (128x64), thread tile 8 rows x 4 cols ----
    float o[8][4] = {};
#pragma unroll 4
    for (int kk = 0; kk < 128; kk++) {
        float4 vv = *(const float4*)(Vs + kk * 64 + tx * 4);
#pragma unroll
        for (int i = 0; i < 8; i++) {
            float a = S[(ri + i) * 128 + kk];
            o[i][0] += a * vv.x;
            o[i][1] += a * vv.y;
            o[i][2] += a * vv.z;
            o[i][3] += a * vv.w;
        }
    }

    // ---- epilogue ----
    if (stage == 1) {
        // xv[b][n][h][w][d]: h = ri+i, w = x_, d = tx*4..+3
        const int obase = b8n * 1048576 + x_ * 64 + tx * 4;
#pragma unroll
        for (int i = 0; i < 8; i++) {
            float4 o4 = { o[i][0], o[i][1], o[i][2], o[i][3] };
            *(float4*)(g_XV + obase + (ri + i) * 8192) = o4;
        }
    } else {
        // out[b][h][w][d*8+n]: w = ri+i, d = tx*4..+3, h = x_
        const int n = b8n & 7;
        const int b = b8n >> 3;
        const int obase = (b * 128 + x_) * 65536 + (tx * 4) * 8 + n;
#pragma unroll
        for (int i = 0; i < 8; i++) {
#pragma unroll
            for (int j = 0; j < 4; j++)
                out[obase + (ri + i) * 512 + j * 8] = o[i][j];
        }
    }
}

// ---------------------------------------------------------------------------
extern "C" void kernel_launch(void* const* d_in, const int* in_sizes, int n_in,
                              void* d_out, int out_size)
{
    const float* x  = (const float*)d_in[0];
    const float* wq = (const float*)d_in[1];
    const float* bq = (const float*)d_in[2];
    const float* wk = (const float*)d_in[3];
    const float* bk = (const float*)d_in[4];
    const float* wv = (const float*)d_in[5];
    const float* bv = (const float*)d_in[6];
    float* out = (float*)d_out;

    const int smemA = 41216 * (int)sizeof(float);   // 164,864 B
    cudaFuncSetAttribute((const void*)attn_kernel,
                         cudaFuncAttributeMaxDynamicSharedMemorySize, smemA);

    dim3 pg(1024, 8, 3);
    proj_kernel<<<pg, 256>>>(x, wq, bq, wk, bk, wv, bv);

    dim3 ag(128, 8, 4);
    attn_kernel<<<ag, 256, smemA>>>(out, 1);
    attn_kernel<<<ag, 256, smemA>>>(out, 2);
}

// round 6
// speedup vs baseline: 1.8941x; 1.8941x over previous
#include <cuda_runtime.h>
#include <cuda_bf16.h>
#include <cstdint>

#define EPSI 1e-7f

// ===========================================================================
// Scratch (__device__ globals; no allocation allowed).
// Q,K,V fp32 [B][nh][W][H][d]; XV fp32 [B][nh][H][W][d].
// Xhi/Xlo: bf16 split of x, [pix][c].  Whi/Wlo: bf16 split of W^T, [p][f][c].
// ===========================================================================
__device__ float g_Q[33554432];
__device__ float g_K[33554432];
__device__ float g_V[33554432];
__device__ float g_XV[33554432];
__device__ __nv_bfloat16 g_Xhi[33554432];
__device__ __nv_bfloat16 g_Xlo[33554432];
__device__ __nv_bfloat16 g_Whi[786432];
__device__ __nv_bfloat16 g_Wlo[786432];

// ===========================================================================
// Helpers: sm_80-era tensor path (compiles on plain compute_103 target)
// ===========================================================================
__device__ __forceinline__ uint32_t smem_u32(const void* p) {
    uint32_t a;
    asm("{ .reg .u64 t; cvta.to.shared.u64 t, %1; cvt.u32.u64 %0, t; }"
        : "=r"(a) : "l"(p));
    return a;
}

#define LDMX4(r, addr) \
    asm volatile("ldmatrix.sync.aligned.m8n8.x4.shared.b16 {%0,%1,%2,%3}, [%4];" \
        : "=r"((r)[0]), "=r"((r)[1]), "=r"((r)[2]), "=r"((r)[3]) : "r"(addr))

__device__ __forceinline__ void mma16816(float* d, const uint32_t* a, const uint32_t* b) {
    asm volatile(
        "mma.sync.aligned.m16n8k16.row.col.f32.bf16.bf16.f32 "
        "{%0,%1,%2,%3}, {%4,%5,%6,%7}, {%8,%9}, {%0,%1,%2,%3};"
        : "+f"(d[0]), "+f"(d[1]), "+f"(d[2]), "+f"(d[3])
        : "r"(a[0]), "r"(a[1]), "r"(a[2]), "r"(a[3]), "r"(b[0]), "r"(b[1]));
}

#define CP16(dst, src) \
    asm volatile("cp.async.cg.shared.global [%0], [%1], 16;" \
        :: "r"(dst), "l"((const void*)(src)))

// ===========================================================================
// x -> bf16 hi/lo split (one float4 per thread; 8,388,608 float4s)
// ===========================================================================
__global__ void __launch_bounds__(256) xsplit_kernel(const float* __restrict__ x)
{
    const int i = blockIdx.x * 256 + threadIdx.x;
    float4 v = ((const float4*)x)[i];
    __nv_bfloat16 h0 = __float2bfloat16(v.x);
    __nv_bfloat16 h1 = __float2bfloat16(v.y);
    __nv_bfloat16 h2 = __float2bfloat16(v.z);
    __nv_bfloat16 h3 = __float2bfloat16(v.w);
    __nv_bfloat162 hp0; hp0.x = h0; hp0.y = h1;
    __nv_bfloat162 hp1; hp1.x = h2; hp1.y = h3;
    __nv_bfloat162 lp0;
    lp0.x = __float2bfloat16(v.x - __bfloat162float(h0));
    lp0.y = __float2bfloat16(v.y - __bfloat162float(h1));
    __nv_bfloat162 lp1;
    lp1.x = __float2bfloat16(v.z - __bfloat162float(h2));
    lp1.y = __float2bfloat16(v.w - __bfloat162float(h3));
    ((__nv_bfloat162*)g_Xhi)[i * 2 + 0] = hp0;
    ((__nv_bfloat162*)g_Xhi)[i * 2 + 1] = hp1;
    ((__nv_bfloat162*)g_Xlo)[i * 2 + 0] = lp0;
    ((__nv_bfloat162*)g_Xlo)[i * 2 + 1] = lp1;
}

// ===========================================================================
// W -> transposed bf16 hi/lo split: WT[p][f][c] = W_p[c][f]   (786,432 elems)
// ===========================================================================
__global__ void __launch_bounds__(256) wsplit_kernel(
    const float* __restrict__ wq, const float* __restrict__ wk,
    const float* __restrict__ wv)
{
    const int idx = blockIdx.x * 256 + threadIdx.x;
    const int p = idx >> 18;
    const int f = (idx >> 9) & 511;
    const int c = idx & 511;
    const float* __restrict__ W = (p == 0) ? wq : (p == 1) ? wk : wv;
    const float v = W[c * 512 + f];
    __nv_bfloat16 h = __float2bfloat16(v);
    g_Whi[idx] = h;
    g_Wlo[idx] = __float2bfloat16(v - __bfloat162float(h));
}

// ===========================================================================
// Projection via warp-level mma.sync (bf16x3 split, fp32 register accums).
// D[128 pix][128 f] per CTA, K=512 in 16 chunks of 32.
// 8 warps: wm=wid&3 (32-row strips), wn=wid>>2 (64-col strips).
// smem: 2 stages x [Ahi | Alo | Bhi | Blo], each tile 128 rows x 80B pitch
//   (32 bf16 data + 16B pad -> conflict-free ldmatrix). Stage = 40,960 B.
// ===========================================================================
#define TPITCH 80
#define TILE_B 10240
#define STAGE_B 40960
#define PROJ_SMEM 81920

__global__ void __launch_bounds__(256) proj_mma_kernel(
    const float* __restrict__ bq, const float* __restrict__ bk,
    const float* __restrict__ bv)
{
    extern __shared__ char smc[];
    const uint32_t sb = smem_u32(smc);

    const int tid  = threadIdx.x;
    const int lane = tid & 31;
    const int wid  = tid >> 5;
    const int wm   = wid & 3;
    const int wn   = wid >> 2;
    const int m0   = blockIdx.x * 128;
    const int n0   = blockIdx.y * 128;
    const int which = blockIdx.z;

    const __nv_bfloat16* __restrict__ Bh = g_Whi + which * 262144;
    const __nv_bfloat16* __restrict__ Bl = g_Wlo + which * 262144;
    const float* __restrict__ bias = (which == 0) ? bq : (which == 1) ? bk : bv;
    float* __restrict__ outp = (which == 0) ? g_Q : (which == 1) ? g_K : g_V;

    // per-thread load mapping (two iterations cover 512 (row,chunk) pairs)
    const int r0a = tid >> 2;          // row 0..63 (iter 0), +64 (iter 1)
    const int ch  = tid & 3;           // 16B chunk within 64B of row data

    float acc[2][8][4];
#pragma unroll
    for (int a = 0; a < 2; a++)
#pragma unroll
        for (int b = 0; b < 8; b++)
#pragma unroll
            for (int c = 0; c < 4; c++) acc[a][b][c] = 0.0f;

    // ---- async-copy one K-chunk into stage buffer ----
    auto issue = [&](int c) {
        const int k0 = c * 32;
        const uint32_t st = sb + (c & 1) * STAGE_B;
#pragma unroll
        for (int i = 0; i < 2; i++) {
            const int row = r0a + i * 64;
            const uint32_t off = row * TPITCH + ch * 16;
            const int ga = (m0 + row) * 512 + k0 + ch * 8;
            const int gb = (n0 + row) * 512 + k0 + ch * 8;
            CP16(st + off,              g_Xhi + ga);
            CP16(st + TILE_B + off,     g_Xlo + ga);
            CP16(st + 2 * TILE_B + off, Bh + gb);
            CP16(st + 3 * TILE_B + off, Bl + gb);
        }
        asm volatile("cp.async.commit_group;");
    };

    issue(0);
    for (int c = 0; c < 16; c++) {
        if (c < 15) {
            issue(c + 1);
            asm volatile("cp.async.wait_group 1;");
        } else {
            asm volatile("cp.async.wait_group 0;");
        }
        __syncthreads();

        const uint32_t st = sb + (c & 1) * STAGE_B;
#pragma unroll
        for (int ks = 0; ks < 2; ks++) {
            // A fragments (hi, lo), 2 m16-tiles
            uint32_t a_hi[2][4], a_lo[2][4];
            const int al = lane & 15;
            const int ac = ks * 2 + (lane >> 4);
#pragma unroll
            for (int mt = 0; mt < 2; mt++) {
                const uint32_t ad = st + (wm * 32 + mt * 16 + al) * TPITCH + ac * 16;
                LDMX4(a_hi[mt], ad);
                LDMX4(a_lo[mt], ad + TILE_B);
            }
            // B fragments (hi, lo), 8 n8-tiles (two per ldmatrix.x4)
            uint32_t b_hi[8][2], b_lo[8][2];
            const int br = (lane >> 4) * 8 + (lane & 7);
            const int bc = ks * 2 + ((lane >> 3) & 1);
#pragma unroll
            for (int p = 0; p < 4; p++) {
                const uint32_t bd = st + 2 * TILE_B
                                  + (wn * 64 + p * 16 + br) * TPITCH + bc * 16;
                uint32_t r[4];
                LDMX4(r, bd);
                b_hi[2 * p][0] = r[0]; b_hi[2 * p][1] = r[1];
                b_hi[2 * p + 1][0] = r[2]; b_hi[2 * p + 1][1] = r[3];
                LDMX4(r, bd + TILE_B);
                b_lo[2 * p][0] = r[0]; b_lo[2 * p][1] = r[1];
                b_lo[2 * p + 1][0] = r[2]; b_lo[2 * p + 1][1] = r[3];
            }
#pragma unroll
            for (int mt = 0; mt < 2; mt++)
#pragma unroll
                for (int nt = 0; nt < 8; nt++) {
                    mma16816(acc[mt][nt], a_hi[mt], b_hi[nt]);
                    mma16816(acc[mt][nt], a_hi[mt], b_lo[nt]);
                    mma16816(acc[mt][nt], a_lo[mt], b_hi[nt]);
                }
        }
        __syncthreads();
    }

    // ---- epilogue: bias + scatter into [B][nh][W][H][d] ----
    const int g  = lane >> 2;
    const int tg = lane & 3;
#pragma unroll
    for (int mt = 0; mt < 2; mt++) {
#pragma unroll
        for (int half = 0; half < 2; half++) {
            const int pix = m0 + wm * 32 + mt * 16 + g + half * 8;
            const int b = pix >> 14;
            const int h = (pix >> 7) & 127;
            const int w = pix & 127;
#pragma unroll
            for (int nt = 0; nt < 8; nt++) {
                const int f  = n0 + wn * 64 + nt * 8 + tg * 2;
                const int nh = f >> 6;
                const int dd = f & 63;
                float2 bb = *(const float2*)(bias + f);
                float2 o;
                o.x = acc[mt][nt][half * 2 + 0] + bb.x;
                o.y = acc[mt][nt][half * 2 + 1] + bb.y;
                float* op = outp + (((b * 8 + nh) * 128 + w) * 128 + h) * 64 + dd;
                *(float2*)op = o;
            }
        }
    }
}

// ---------------------------------------------------------------------------
// Axial attention (unchanged from the passing round-1 kernel).
// ---------------------------------------------------------------------------
__global__ void __launch_bounds__(256) attn_kernel(float* __restrict__ out, const int stage)
{
    extern __shared__ float smem[];
    float* S   = smem;            // 128*128
    float* Qs  = smem + 16384;    // 128*64
    float* KsT = smem + 24576;    // 64*132
    float* Vs  = smem + 33024;    // 128*64

    const int tid = threadIdx.x;
    const int x_  = blockIdx.x;
    const int b8n = blockIdx.z * 8 + blockIdx.y;

    const float* __restrict__ Qg = g_Q;
    const float* __restrict__ Kg = g_K;
    const float* __restrict__ Vg = (stage == 1) ? g_V : g_XV;

    int qbase, rstride, vbase;
    if (stage == 1) {
        qbase   = (b8n * 128 + x_) * 8192;
        rstride = 64;
        vbase   = qbase;
    } else {
        qbase   = b8n * 1048576 + x_ * 64;
        rstride = 8192;
        vbase   = (b8n * 128 + x_) * 8192;
    }

    for (int idx = tid; idx < 2048; idx += 256) {
        const int dd4 = (idx & 15) * 4;
        const int row = idx >> 4;
        const int goff = qbase + row * rstride + dd4;
        float4 q4 = *(const float4*)(Qg + goff);
        *(float4*)(Qs + row * 64 + dd4) = q4;
        float4 k4 = *(const float4*)(Kg + goff);
        KsT[(dd4 + 0) * 132 + row] = k4.x;
        KsT[(dd4 + 1) * 132 + row] = k4.y;
        KsT[(dd4 + 2) * 132 + row] = k4.z;
        KsT[(dd4 + 3) * 132 + row] = k4.w;
        *(float4*)(Vs + idx * 4) = *(const float4*)(Vg + vbase + idx * 4);
    }
    __syncthreads();

    const int tx = tid & 15, ty = tid >> 4;
    const int ri = ty * 8, cj = tx * 8;
    {
        float acc[8][8] = {};
#pragma unroll 8
        for (int kk = 0; kk < 64; kk++) {
            float a[8];
#pragma unroll
            for (int i = 0; i < 8; i++) a[i] = Qs[(ri + i) * 64 + kk];
            float4 b0 = *(const float4*)(KsT + kk * 132 + cj);
            float4 b1 = *(const float4*)(KsT + kk * 132 + cj + 4);
            float bb[8] = { b0.x, b0.y, b0.z, b0.w, b1.x, b1.y, b1.z, b1.w };
#pragma unroll
            for (int i = 0; i < 8; i++)
#pragma unroll
                for (int j = 0; j < 8; j++)
                    acc[i][j] += a[i] * bb[j];
        }
        const float lo = -1.0f + EPSI, hi = 1.0f - EPSI;
#pragma unroll
        for (int i = 0; i < 8; i++) {
#pragma unroll
            for (int j = 0; j < 8; j++) {
                S[(ri + i) * 128 + cj + j] =
                    fminf(fmaxf(acc[i][j], lo), hi) * 0.125f;
            }
        }
    }
    __syncthreads();

    {
        const int wid = tid >> 5, lane = tid & 31;
        for (int rr = 0; rr < 16; rr++) {
            float* srow = S + (wid * 16 + rr) * 128;
            float v0 = srow[lane];
            float v1 = srow[lane + 32];
            float v2 = srow[lane + 64];
            float v3 = srow[lane + 96];
            float mx = fmaxf(fmaxf(v0, v1), fmaxf(v2, v3));
#pragma unroll
            for (int off = 16; off; off >>= 1)
                mx = fmaxf(mx, __shfl_xor_sync(0xffffffffu, mx, off));
            float e0 = __expf(v0 - mx);
            float e1 = __expf(v1 - mx);
            float e2 = __expf(v2 - mx);
            float e3 = __expf(v3 - mx);
            float s = e0 + e1 + e2 + e3;
#pragma unroll
            for (int off = 16; off; off >>= 1)
                s += __shfl_xor_sync(0xffffffffu, s, off);
            const float inv = 1.0f / s;
            const float alo = EPSI, ahi = 1.0f - EPSI;
            srow[lane]      = fminf(fmaxf(e0 * inv, alo), ahi);
            srow[lane + 32] = fminf(fmaxf(e1 * inv, alo), ahi);
            srow[lane + 64] = fminf(fmaxf(e2 * inv, alo), ahi);
            srow[lane + 96] = fminf(fmaxf(e3 * inv, alo), ahi);
        }
    }
    __syncthreads();

    float o[8][4] = {};
#pragma unroll 4
    for (int kk = 0; kk < 128; kk++) {
        float4 vv = *(const float4*)(Vs + kk * 64 + tx * 4);
#pragma unroll
        for (int i = 0; i < 8; i++) {
            float a = S[(ri + i) * 128 + kk];
            o[i][0] += a * vv.x;
            o[i][1] += a * vv.y;
            o[i][2] += a * vv.z;
            o[i][3] += a * vv.w;
        }
    }

    if (stage == 1) {
        const int obase = b8n * 1048576 + x_ * 64 + tx * 4;
#pragma unroll
        for (int i = 0; i < 8; i++) {
            float4 o4 = { o[i][0], o[i][1], o[i][2], o[i][3] };
            *(float4*)(g_XV + obase + (ri + i) * 8192) = o4;
        }
    } else {
        const int n = b8n & 7;
        const int b = b8n >> 3;
        const int obase = (b * 128 + x_) * 65536 + (tx * 4) * 8 + n;
#pragma unroll
        for (int i = 0; i < 8; i++) {
#pragma unroll
            for (int j = 0; j < 4; j++)
                out[obase + (ri + i) * 512 + j * 8] = o[i][j];
        }
    }
}

// ---------------------------------------------------------------------------
extern "C" void kernel_launch(void* const* d_in, const int* in_sizes, int n_in,
                              void* d_out, int out_size)
{
    const float* x  = (const float*)d_in[0];
    const float* wq = (const float*)d_in[1];
    const float* bq = (const float*)d_in[2];
    const float* wk = (const float*)d_in[3];
    const float* bk = (const float*)d_in[4];
    const float* wv = (const float*)d_in[5];
    const float* bv = (const float*)d_in[6];
    float* out = (float*)d_out;

    const int smemA = 41216 * (int)sizeof(float);   // 164,864 B
    cudaFuncSetAttribute((const void*)attn_kernel,
                         cudaFuncAttributeMaxDynamicSharedMemorySize, smemA);
    cudaFuncSetAttribute((const void*)proj_mma_kernel,
                         cudaFuncAttributeMaxDynamicSharedMemorySize, PROJ_SMEM);

    xsplit_kernel<<<32768, 256>>>(x);
    wsplit_kernel<<<3072, 256>>>(wq, wk, wv);

    dim3 pg(512, 4, 3);
    proj_mma_kernel<<<pg, 256, PROJ_SMEM>>>(bq, bk, bv);

    dim3 ag(128, 8, 4);
    attn_kernel<<<ag, 256, smemA>>>(out, 1);
    attn_kernel<<<ag, 256, smemA>>>(out, 2);
}

// round 7
// speedup vs baseline: 2.4141x; 1.2745x over previous
#include <cuda_runtime.h>
#include <cuda_bf16.h>
#include <cstdint>

#define EPSI 1e-7f

// ===========================================================================
// Scratch (__device__ globals; no allocation allowed).
// Q,K,V fp32 [B][nh][W][H][d]; XV fp32 [B][nh][H][W][d].
// Xhi/Xlo: bf16 split of x, [pix][c].  Whi/Wlo: bf16 split of W^T, [p][f][c].
// ===========================================================================
__device__ float g_Q[33554432];
__device__ float g_K[33554432];
__device__ float g_V[33554432];
__device__ float g_XV[33554432];
__device__ __nv_bfloat16 g_Xhi[33554432];
__device__ __nv_bfloat16 g_Xlo[33554432];
__device__ __nv_bfloat16 g_Whi[786432];
__device__ __nv_bfloat16 g_Wlo[786432];

// ===========================================================================
// Helpers: sm_80-era tensor path (compiles on plain compute_103 target)
// ===========================================================================
__device__ __forceinline__ uint32_t smem_u32(const void* p) {
    uint32_t a;
    asm("{ .reg .u64 t; cvta.to.shared.u64 t, %1; cvt.u32.u64 %0, t; }"
        : "=r"(a) : "l"(p));
    return a;
}

#define LDMX4(r, addr) \
    asm volatile("ldmatrix.sync.aligned.m8n8.x4.shared.b16 {%0,%1,%2,%3}, [%4];" \
        : "=r"((r)[0]), "=r"((r)[1]), "=r"((r)[2]), "=r"((r)[3]) : "r"(addr))

__device__ __forceinline__ void mma16816(float* d, const uint32_t* a, const uint32_t* b) {
    asm volatile(
        "mma.sync.aligned.m16n8k16.row.col.f32.bf16.bf16.f32 "
        "{%0,%1,%2,%3}, {%4,%5,%6,%7}, {%8,%9}, {%0,%1,%2,%3};"
        : "+f"(d[0]), "+f"(d[1]), "+f"(d[2]), "+f"(d[3])
        : "r"(a[0]), "r"(a[1]), "r"(a[2]), "r"(a[3]), "r"(b[0]), "r"(b[1]));
}

#define CP16(dst, src) \
    asm volatile("cp.async.cg.shared.global [%0], [%1], 16;" \
        :: "r"(dst), "l"((const void*)(src)))

__device__ __forceinline__ uint32_t pack_bf16x2(float f0, float f1) {
    __nv_bfloat162 t = __floats2bfloat162_rn(f0, f1);   // x = f0 (low half)
    return *reinterpret_cast<uint32_t*>(&t);
}

// ===========================================================================
// x -> bf16 hi/lo split
// ===========================================================================
__global__ void __launch_bounds__(256) xsplit_kernel(const float* __restrict__ x)
{
    const int i = blockIdx.x * 256 + threadIdx.x;
    float4 v = ((const float4*)x)[i];
    __nv_bfloat16 h0 = __float2bfloat16(v.x);
    __nv_bfloat16 h1 = __float2bfloat16(v.y);
    __nv_bfloat16 h2 = __float2bfloat16(v.z);
    __nv_bfloat16 h3 = __float2bfloat16(v.w);
    __nv_bfloat162 hp0; hp0.x = h0; hp0.y = h1;
    __nv_bfloat162 hp1; hp1.x = h2; hp1.y = h3;
    __nv_bfloat162 lp0;
    lp0.x = __float2bfloat16(v.x - __bfloat162float(h0));
    lp0.y = __float2bfloat16(v.y - __bfloat162float(h1));
    __nv_bfloat162 lp1;
    lp1.x = __float2bfloat16(v.z - __bfloat162float(h2));
    lp1.y = __float2bfloat16(v.w - __bfloat162float(h3));
    ((__nv_bfloat162*)g_Xhi)[i * 2 + 0] = hp0;
    ((__nv_bfloat162*)g_Xhi)[i * 2 + 1] = hp1;
    ((__nv_bfloat162*)g_Xlo)[i * 2 + 0] = lp0;
    ((__nv_bfloat162*)g_Xlo)[i * 2 + 1] = lp1;
}

// ===========================================================================
// W -> transposed bf16 hi/lo split: WT[p][f][c] = W_p[c][f]
// ===========================================================================
__global__ void __launch_bounds__(256) wsplit_kernel(
    const float* __restrict__ wq, const float* __restrict__ wk,
    const float* __restrict__ wv)
{
    const int idx = blockIdx.x * 256 + threadIdx.x;
    const int p = idx >> 18;
    const int f = (idx >> 9) & 511;
    const int c = idx & 511;
    const float* __restrict__ W = (p == 0) ? wq : (p == 1) ? wk : wv;
    const float v = W[c * 512 + f];
    __nv_bfloat16 h = __float2bfloat16(v);
    g_Whi[idx] = h;
    g_Wlo[idx] = __float2bfloat16(v - __bfloat162float(h));
}

// ===========================================================================
// Projection via warp-level mma.sync (unchanged from R6 — near HMMA floor).
// ===========================================================================
#define TPITCH 80
#define TILE_B 10240
#define STAGE_B 40960
#define PROJ_SMEM 81920

__global__ void __launch_bounds__(256) proj_mma_kernel(
    const float* __restrict__ bq, const float* __restrict__ bk,
    const float* __restrict__ bv)
{
    extern __shared__ char smc[];
    const uint32_t sb = smem_u32(smc);

    const int tid  = threadIdx.x;
    const int lane = tid & 31;
    const int wid  = tid >> 5;
    const int wm   = wid & 3;
    const int wn   = wid >> 2;
    const int m0   = blockIdx.x * 128;
    const int n0   = blockIdx.y * 128;
    const int which = blockIdx.z;

    const __nv_bfloat16* __restrict__ Bh = g_Whi + which * 262144;
    const __nv_bfloat16* __restrict__ Bl = g_Wlo + which * 262144;
    const float* __restrict__ bias = (which == 0) ? bq : (which == 1) ? bk : bv;
    float* __restrict__ outp = (which == 0) ? g_Q : (which == 1) ? g_K : g_V;

    const int r0a = tid >> 2;
    const int ch  = tid & 3;

    float acc[2][8][4];
#pragma unroll
    for (int a = 0; a < 2; a++)
#pragma unroll
        for (int b = 0; b < 8; b++)
#pragma unroll
            for (int c = 0; c < 4; c++) acc[a][b][c] = 0.0f;

    auto issue = [&](int c) {
        const int k0 = c * 32;
        const uint32_t st = sb + (c & 1) * STAGE_B;
#pragma unroll
        for (int i = 0; i < 2; i++) {
            const int row = r0a + i * 64;
            const uint32_t off = row * TPITCH + ch * 16;
            const int ga = (m0 + row) * 512 + k0 + ch * 8;
            const int gb = (n0 + row) * 512 + k0 + ch * 8;
            CP16(st + off,              g_Xhi + ga);
            CP16(st + TILE_B + off,     g_Xlo + ga);
            CP16(st + 2 * TILE_B + off, Bh + gb);
            CP16(st + 3 * TILE_B + off, Bl + gb);
        }
        asm volatile("cp.async.commit_group;");
    };

    issue(0);
    for (int c = 0; c < 16; c++) {
        if (c < 15) {
            issue(c + 1);
            asm volatile("cp.async.wait_group 1;");
        } else {
            asm volatile("cp.async.wait_group 0;");
        }
        __syncthreads();

        const uint32_t st = sb + (c & 1) * STAGE_B;
#pragma unroll
        for (int ks = 0; ks < 2; ks++) {
            uint32_t a_hi[2][4], a_lo[2][4];
            const int al = lane & 15;
            const int ac = ks * 2 + (lane >> 4);
#pragma unroll
            for (int mt = 0; mt < 2; mt++) {
                const uint32_t ad = st + (wm * 32 + mt * 16 + al) * TPITCH + ac * 16;
                LDMX4(a_hi[mt], ad);
                LDMX4(a_lo[mt], ad + TILE_B);
            }
            uint32_t b_hi[8][2], b_lo[8][2];
            const int br = (lane >> 4) * 8 + (lane & 7);
            const int bc = ks * 2 + ((lane >> 3) & 1);
#pragma unroll
            for (int p = 0; p < 4; p++) {
                const uint32_t bd = st + 2 * TILE_B
                                  + (wn * 64 + p * 16 + br) * TPITCH + bc * 16;
                uint32_t r[4];
                LDMX4(r, bd);
                b_hi[2 * p][0] = r[0]; b_hi[2 * p][1] = r[1];
                b_hi[2 * p + 1][0] = r[2]; b_hi[2 * p + 1][1] = r[3];
                LDMX4(r, bd + TILE_B);
                b_lo[2 * p][0] = r[0]; b_lo[2 * p][1] = r[1];
                b_lo[2 * p + 1][0] = r[2]; b_lo[2 * p + 1][1] = r[3];
            }
#pragma unroll
            for (int mt = 0; mt < 2; mt++)
#pragma unroll
                for (int nt = 0; nt < 8; nt++) {
                    mma16816(acc[mt][nt], a_hi[mt], b_hi[nt]);
                    mma16816(acc[mt][nt], a_hi[mt], b_lo[nt]);
                    mma16816(acc[mt][nt], a_lo[mt], b_hi[nt]);
                }
        }
        __syncthreads();
    }

    const int g  = lane >> 2;
    const int tg = lane & 3;
#pragma unroll
    for (int mt = 0; mt < 2; mt++) {
#pragma unroll
        for (int half = 0; half < 2; half++) {
            const int pix = m0 + wm * 32 + mt * 16 + g + half * 8;
            const int b = pix >> 14;
            const int h = (pix >> 7) & 127;
            const int w = pix & 127;
#pragma unroll
            for (int nt = 0; nt < 8; nt++) {
                const int f  = n0 + wn * 64 + nt * 8 + tg * 2;
                const int nh = f >> 6;
                const int dd = f & 63;
                float2 bb = *(const float2*)(bias + f);
                float2 o;
                o.x = acc[mt][nt][half * 2 + 0] + bb.x;
                o.y = acc[mt][nt][half * 2 + 1] + bb.y;
                float* op = outp + (((b * 8 + nh) * 128 + w) * 128 + h) * 64 + dd;
                *(float2*)op = o;
            }
        }
    }
}

// ===========================================================================
// Tensor-core axial attention.  One CTA per (b, head, line), 256 thr, 8 warps.
// smem (bytes): Qhi 0, Qlo 18432, Khi 36864, Klo 55296 (128 rows x 144B pitch)
//               VThi 73728, VTlo 91136 (64 d-rows x 272B pitch) -> 108,544 B.
// Warp w owns S rows [16w,16w+16).  S accums + softmax + P stay in registers.
// ===========================================================================
#define AQHI 0
#define AQLO 18432
#define AKHI 36864
#define AKLO 55296
#define AVHI 73728
#define AVLO 91136
#define ATTN_SMEM 108544

__global__ void __launch_bounds__(256) attn_mma_kernel(float* __restrict__ out, const int stage)
{
    extern __shared__ char sm[];
    const uint32_t sb = smem_u32(sm);

    const int tid  = threadIdx.x;
    const int lane = tid & 31;
    const int wid  = tid >> 5;
    const int x_   = blockIdx.x;
    const int b8n  = blockIdx.z * 8 + blockIdx.y;

    const float* __restrict__ Qg = g_Q;
    const float* __restrict__ Kg = g_K;
    const float* __restrict__ Vg = (stage == 1) ? g_V : g_XV;

    int qbase, rstride, vbase;
    if (stage == 1) {
        qbase   = (b8n * 128 + x_) * 8192;
        rstride = 64;
        vbase   = qbase;
    } else {
        qbase   = b8n * 1048576 + x_ * 64;
        rstride = 8192;
        vbase   = (b8n * 128 + x_) * 8192;
    }

    // ---- load Q,K (bf16 hi/lo, row-major, pitch 144) ----
    for (int idx = tid; idx < 2048; idx += 256) {
        const int row = idx >> 4;
        const int c4  = idx & 15;
        const int goff = qbase + row * rstride + c4 * 4;
        const uint32_t so = row * 144 + c4 * 8;

        float4 q = *(const float4*)(Qg + goff);
        __nv_bfloat162 qh0, qh1, ql0, ql1;
        qh0.x = __float2bfloat16(q.x); qh0.y = __float2bfloat16(q.y);
        qh1.x = __float2bfloat16(q.z); qh1.y = __float2bfloat16(q.w);
        ql0.x = __float2bfloat16(q.x - __bfloat162float(qh0.x));
        ql0.y = __float2bfloat16(q.y - __bfloat162float(qh0.y));
        ql1.x = __float2bfloat16(q.z - __bfloat162float(qh1.x));
        ql1.y = __float2bfloat16(q.w - __bfloat162float(qh1.y));
        *(__nv_bfloat162*)(sm + AQHI + so)     = qh0;
        *(__nv_bfloat162*)(sm + AQHI + so + 4) = qh1;
        *(__nv_bfloat162*)(sm + AQLO + so)     = ql0;
        *(__nv_bfloat162*)(sm + AQLO + so + 4) = ql1;

        float4 k = *(const float4*)(Kg + goff);
        __nv_bfloat162 kh0, kh1, kl0, kl1;
        kh0.x = __float2bfloat16(k.x); kh0.y = __float2bfloat16(k.y);
        kh1.x = __float2bfloat16(k.z); kh1.y = __float2bfloat16(k.w);
        kl0.x = __float2bfloat16(k.x - __bfloat162float(kh0.x));
        kl0.y = __float2bfloat16(k.y - __bfloat162float(kh0.y));
        kl1.x = __float2bfloat16(k.z - __bfloat162float(kh1.x));
        kl1.y = __float2bfloat16(k.w - __bfloat162float(kh1.y));
        *(__nv_bfloat162*)(sm + AKHI + so)     = kh0;
        *(__nv_bfloat162*)(sm + AKHI + so + 4) = kh1;
        *(__nv_bfloat162*)(sm + AKLO + so)     = kl0;
        *(__nv_bfloat162*)(sm + AKLO + so + 4) = kl1;
    }
    // ---- load V transposed: VT[d][seq] (pitch 272) ----
    for (int idx = tid; idx < 2048; idx += 256) {
        const int seq = idx >> 4;
        const int c4  = idx & 15;
        float4 v = *(const float4*)(Vg + vbase + seq * 64 + c4 * 4);
        const float vv[4] = { v.x, v.y, v.z, v.w };
#pragma unroll
        for (int k = 0; k < 4; k++) {
            const int d = c4 * 4 + k;
            __nv_bfloat16 h = __float2bfloat16(vv[k]);
            __nv_bfloat16 l = __float2bfloat16(vv[k] - __bfloat162float(h));
            *(__nv_bfloat16*)(sm + AVHI + d * 272 + seq * 2) = h;
            *(__nv_bfloat16*)(sm + AVLO + d * 272 + seq * 2) = l;
        }
    }
    __syncthreads();

    // ---- S = Q * K^T  (warp strip m16 x N=128), bf16x3 ----
    float sacc[16][4];
#pragma unroll
    for (int j = 0; j < 16; j++)
#pragma unroll
        for (int c = 0; c < 4; c++) sacc[j][c] = 0.0f;

    const int m0w = wid * 16;
    const int alr = lane & 15;
    const int alc = lane >> 4;
    const int blr = ((lane >> 4) << 3) + (lane & 7);
    const int blc = (lane >> 3) & 1;

#pragma unroll
    for (int kt = 0; kt < 4; kt++) {
        uint32_t ahi[4], alo[4];
        const uint32_t aa = sb + AQHI + (m0w + alr) * 144 + (kt * 2 + alc) * 16;
        LDMX4(ahi, aa);
        LDMX4(alo, aa + (AQLO - AQHI));
#pragma unroll
        for (int p = 0; p < 8; p++) {
            const uint32_t ba = sb + AKHI + (p * 16 + blr) * 144 + (kt * 2 + blc) * 16;
            uint32_t bh[4], bl[4];
            LDMX4(bh, ba);
            LDMX4(bl, ba + (AKLO - AKHI));
            mma16816(sacc[2 * p],     ahi, &bh[0]);
            mma16816(sacc[2 * p],     ahi, &bl[0]);
            mma16816(sacc[2 * p],     alo, &bh[0]);
            mma16816(sacc[2 * p + 1], ahi, &bh[2]);
            mma16816(sacc[2 * p + 1], ahi, &bl[2]);
            mma16816(sacc[2 * p + 1], alo, &bh[2]);
        }
    }

    // ---- clip(+-(1-eps)), /8, softmax per row (rows live in 4-lane groups) ----
    {
        const float lo = -1.0f + EPSI, hi = 1.0f - EPSI;
#pragma unroll
        for (int j = 0; j < 16; j++)
#pragma unroll
            for (int c = 0; c < 4; c++)
                sacc[j][c] = fminf(fmaxf(sacc[j][c], lo), hi) * 0.125f;

        float mx0 = -1e30f, mx1 = -1e30f;
#pragma unroll
        for (int j = 0; j < 16; j++) {
            mx0 = fmaxf(mx0, fmaxf(sacc[j][0], sacc[j][1]));
            mx1 = fmaxf(mx1, fmaxf(sacc[j][2], sacc[j][3]));
        }
        mx0 = fmaxf(mx0, __shfl_xor_sync(0xffffffffu, mx0, 1));
        mx0 = fmaxf(mx0, __shfl_xor_sync(0xffffffffu, mx0, 2));
        mx1 = fmaxf(mx1, __shfl_xor_sync(0xffffffffu, mx1, 1));
        mx1 = fmaxf(mx1, __shfl_xor_sync(0xffffffffu, mx1, 2));

        float s0 = 0.0f, s1 = 0.0f;
#pragma unroll
        for (int j = 0; j < 16; j++) {
            sacc[j][0] = __expf(sacc[j][0] - mx0);
            sacc[j][1] = __expf(sacc[j][1] - mx0);
            sacc[j][2] = __expf(sacc[j][2] - mx1);
            sacc[j][3] = __expf(sacc[j][3] - mx1);
            s0 += sacc[j][0] + sacc[j][1];
            s1 += sacc[j][2] + sacc[j][3];
        }
        s0 += __shfl_xor_sync(0xffffffffu, s0, 1);
        s0 += __shfl_xor_sync(0xffffffffu, s0, 2);
        s1 += __shfl_xor_sync(0xffffffffu, s1, 1);
        s1 += __shfl_xor_sync(0xffffffffu, s1, 2);
        const float i0 = 1.0f / s0, i1 = 1.0f / s1;
        const float alo2 = EPSI, ahi2 = 1.0f - EPSI;
#pragma unroll
        for (int j = 0; j < 16; j++) {
            sacc[j][0] = fminf(fmaxf(sacc[j][0] * i0, alo2), ahi2);
            sacc[j][1] = fminf(fmaxf(sacc[j][1] * i0, alo2), ahi2);
            sacc[j][2] = fminf(fmaxf(sacc[j][2] * i1, alo2), ahi2);
            sacc[j][3] = fminf(fmaxf(sacc[j][3] * i1, alo2), ahi2);
        }
    }

    // ---- O = P * V  (m16 x N=64, K=128), P hi/lo from registers ----
    float oacc[8][4];
#pragma unroll
    for (int j = 0; j < 8; j++)
#pragma unroll
        for (int c = 0; c < 4; c++) oacc[j][c] = 0.0f;

#pragma unroll
    for (int jj = 0; jj < 8; jj++) {
        const int e = 2 * jj, o = 2 * jj + 1;
        uint32_t phi[4], plo[4];
        // a0=(g, c01 of even), a1=(g+8, even), a2=(g, odd), a3=(g+8, odd)
        {
            float p00 = sacc[e][0], p01 = sacc[e][1];
            float p02 = sacc[e][2], p03 = sacc[e][3];
            float p10 = sacc[o][0], p11 = sacc[o][1];
            float p12 = sacc[o][2], p13 = sacc[o][3];
            __nv_bfloat16 h;
            float r0, r1;
            phi[0] = pack_bf16x2(p00, p01);
            h = __float2bfloat16(p00); r0 = p00 - __bfloat162float(h);
            h = __float2bfloat16(p01); r1 = p01 - __bfloat162float(h);
            plo[0] = pack_bf16x2(r0, r1);
            phi[1] = pack_bf16x2(p02, p03);
            h = __float2bfloat16(p02); r0 = p02 - __bfloat162float(h);
            h = __float2bfloat16(p03); r1 = p03 - __bfloat162float(h);
            plo[1] = pack_bf16x2(r0, r1);
            phi[2] = pack_bf16x2(p10, p11);
            h = __float2bfloat16(p10); r0 = p10 - __bfloat162float(h);
            h = __float2bfloat16(p11); r1 = p11 - __bfloat162float(h);
            plo[2] = pack_bf16x2(r0, r1);
            phi[3] = pack_bf16x2(p12, p13);
            h = __float2bfloat16(p12); r0 = p12 - __bfloat162float(h);
            h = __float2bfloat16(p13); r1 = p13 - __bfloat162float(h);
            plo[3] = pack_bf16x2(r0, r1);
        }
#pragma unroll
        for (int np = 0; np < 4; np++) {
            const uint32_t ba = sb + AVHI + (np * 16 + blr) * 272 + (jj * 2 + blc) * 16;
            uint32_t bh[4], bl[4];
            LDMX4(bh, ba);
            LDMX4(bl, ba + (AVLO - AVHI));
            mma16816(oacc[2 * np],     phi, &bh[0]);
            mma16816(oacc[2 * np],     phi, &bl[0]);
            mma16816(oacc[2 * np],     plo, &bh[0]);
            mma16816(oacc[2 * np + 1], phi, &bh[2]);
            mma16816(oacc[2 * np + 1], phi, &bl[2]);
            mma16816(oacc[2 * np + 1], plo, &bh[2]);
        }
    }

    // ---- epilogue ----
    const int g  = lane >> 2;
    const int t4 = lane & 3;
    if (stage == 1) {
        // g_XV[b][n][h][w][d]: row = h, col = d, w = x_
        const int base = b8n * 1048576 + x_ * 64;
#pragma unroll
        for (int nt = 0; nt < 8; nt++) {
            const int d = nt * 8 + t4 * 2;
            float2 o0 = { oacc[nt][0], oacc[nt][1] };
            float2 o1 = { oacc[nt][2], oacc[nt][3] };
            *(float2*)(g_XV + base + (m0w + g) * 8192 + d)     = o0;
            *(float2*)(g_XV + base + (m0w + g + 8) * 8192 + d) = o1;
        }
    } else {
        // out[b][h=x_][w=row][c=d*8+n]
        const int n = b8n & 7;
        const int b = b8n >> 3;
        const int base = (b * 128 + x_) * 65536 + n;
#pragma unroll
        for (int nt = 0; nt < 8; nt++) {
            const int d = nt * 8 + t4 * 2;
            out[base + (m0w + g) * 512 + d * 8]           = oacc[nt][0];
            out[base + (m0w + g) * 512 + (d + 1) * 8]     = oacc[nt][1];
            out[base + (m0w + g + 8) * 512 + d * 8]       = oacc[nt][2];
            out[base + (m0w + g + 8) * 512 + (d + 1) * 8] = oacc[nt][3];
        }
    }
}

// ---------------------------------------------------------------------------
extern "C" void kernel_launch(void* const* d_in, const int* in_sizes, int n_in,
                              void* d_out, int out_size)
{
    const float* x  = (const float*)d_in[0];
    const float* wq = (const float*)d_in[1];
    const float* bq = (const float*)d_in[2];
    const float* wk = (const float*)d_in[3];
    const float* bk = (const float*)d_in[4];
    const float* wv = (const float*)d_in[5];
    const float* bv = (const float*)d_in[6];
    float* out = (float*)d_out;

    cudaFuncSetAttribute((const void*)attn_mma_kernel,
                         cudaFuncAttributeMaxDynamicSharedMemorySize, ATTN_SMEM);
    cudaFuncSetAttribute((const void*)proj_mma_kernel,
                         cudaFuncAttributeMaxDynamicSharedMemorySize, PROJ_SMEM);

    xsplit_kernel<<<32768, 256>>>(x);
    wsplit_kernel<<<3072, 256>>>(wq, wk, wv);

    dim3 pg(512, 4, 3);
    proj_mma_kernel<<<pg, 256, PROJ_SMEM>>>(bq, bk, bv);

    dim3 ag(128, 8, 4);
    attn_mma_kernel<<<ag, 256, ATTN_SMEM>>>(out, 1);
    attn_mma_kernel<<<ag, 256, ATTN_SMEM>>>(out, 2);
}

// round 8
// speedup vs baseline: 2.8045x; 1.1617x over previous
#include <cuda_runtime.h>
#include <cuda_bf16.h>
#include <cstdint>

#define EPSI 1e-7f

// ===========================================================================
// Scratch (__device__ globals; no allocation allowed).
// Qh/Ql,Kh/Kl,Vh/Vl: bf16 hi/lo, [B][nh][W][H][d].
// XVh/XVl: bf16 hi/lo, [B][nh][H][W][d].
// Xhi/Xlo: bf16 split of x, [pix][c].  Whi/Wlo: bf16 split of W^T, [p][f][c].
// ===========================================================================
__device__ __nv_bfloat16 g_Qh[33554432];
__device__ __nv_bfloat16 g_Ql[33554432];
__device__ __nv_bfloat16 g_Kh[33554432];
__device__ __nv_bfloat16 g_Kl[33554432];
__device__ __nv_bfloat16 g_Vh[33554432];
__device__ __nv_bfloat16 g_Vl[33554432];
__device__ __nv_bfloat16 g_XVh[33554432];
__device__ __nv_bfloat16 g_XVl[33554432];
__device__ __nv_bfloat16 g_Xhi[33554432];
__device__ __nv_bfloat16 g_Xlo[33554432];
__device__ __nv_bfloat16 g_Whi[786432];
__device__ __nv_bfloat16 g_Wlo[786432];

// ===========================================================================
// Helpers (sm_80-era tensor path; compiles on plain compute_103 target)
// ===========================================================================
__device__ __forceinline__ uint32_t smem_u32(const void* p) {
    uint32_t a;
    asm("{ .reg .u64 t; cvta.to.shared.u64 t, %1; cvt.u32.u64 %0, t; }"
        : "=r"(a) : "l"(p));
    return a;
}

#define LDMX4(r, addr) \
    asm volatile("ldmatrix.sync.aligned.m8n8.x4.shared.b16 {%0,%1,%2,%3}, [%4];" \
        : "=r"((r)[0]), "=r"((r)[1]), "=r"((r)[2]), "=r"((r)[3]) : "r"(addr))

#define LDMX4T(r, addr) \
    asm volatile("ldmatrix.sync.aligned.m8n8.x4.trans.shared.b16 {%0,%1,%2,%3}, [%4];" \
        : "=r"((r)[0]), "=r"((r)[1]), "=r"((r)[2]), "=r"((r)[3]) : "r"(addr))

__device__ __forceinline__ void mma16816(float* d, const uint32_t* a, const uint32_t* b) {
    asm volatile(
        "mma.sync.aligned.m16n8k16.row.col.f32.bf16.bf16.f32 "
        "{%0,%1,%2,%3}, {%4,%5,%6,%7}, {%8,%9}, {%0,%1,%2,%3};"
        : "+f"(d[0]), "+f"(d[1]), "+f"(d[2]), "+f"(d[3])
        : "r"(a[0]), "r"(a[1]), "r"(a[2]), "r"(a[3]), "r"(b[0]), "r"(b[1]));
}

#define CP16(dst, src) \
    asm volatile("cp.async.cg.shared.global [%0], [%1], 16;" \
        :: "r"(dst), "l"((const void*)(src)))

__device__ __forceinline__ uint32_t pack_bf16x2(float f0, float f1) {
    __nv_bfloat162 t = __floats2bfloat162_rn(f0, f1);   // x = f0 (low half)
    return *reinterpret_cast<uint32_t*>(&t);
}

// SW128 swizzle on byte offsets (rows are 128 B)
#define ASW(off) ((uint32_t)(off) ^ ((((uint32_t)(off)) >> 3) & 0x70u))

// ===========================================================================
// x -> bf16 hi/lo split
// ===========================================================================
__global__ void __launch_bounds__(256) xsplit_kernel(const float* __restrict__ x)
{
    const int i = blockIdx.x * 256 + threadIdx.x;
    float4 v = ((const float4*)x)[i];
    __nv_bfloat16 h0 = __float2bfloat16(v.x);
    __nv_bfloat16 h1 = __float2bfloat16(v.y);
    __nv_bfloat16 h2 = __float2bfloat16(v.z);
    __nv_bfloat16 h3 = __float2bfloat16(v.w);
    __nv_bfloat162 hp0; hp0.x = h0; hp0.y = h1;
    __nv_bfloat162 hp1; hp1.x = h2; hp1.y = h3;
    __nv_bfloat162 lp0;
    lp0.x = __float2bfloat16(v.x - __bfloat162float(h0));
    lp0.y = __float2bfloat16(v.y - __bfloat162float(h1));
    __nv_bfloat162 lp1;
    lp1.x = __float2bfloat16(v.z - __bfloat162float(h2));
    lp1.y = __float2bfloat16(v.w - __bfloat162float(h3));
    ((__nv_bfloat162*)g_Xhi)[i * 2 + 0] = hp0;
    ((__nv_bfloat162*)g_Xhi)[i * 2 + 1] = hp1;
    ((__nv_bfloat162*)g_Xlo)[i * 2 + 0] = lp0;
    ((__nv_bfloat162*)g_Xlo)[i * 2 + 1] = lp1;
}

// ===========================================================================
// W -> transposed bf16 hi/lo split: WT[p][f][c] = W_p[c][f]
// ===========================================================================
__global__ void __launch_bounds__(256) wsplit_kernel(
    const float* __restrict__ wq, const float* __restrict__ wk,
    const float* __restrict__ wv)
{
    const int idx = blockIdx.x * 256 + threadIdx.x;
    const int p = idx >> 18;
    const int f = (idx >> 9) & 511;
    const int c = idx & 511;
    const float* __restrict__ W = (p == 0) ? wq : (p == 1) ? wk : wv;
    const float v = W[c * 512 + f];
    __nv_bfloat16 h = __float2bfloat16(v);
    g_Whi[idx] = h;
    g_Wlo[idx] = __float2bfloat16(v - __bfloat162float(h));
}

// ===========================================================================
// Projection via warp-level mma.sync (R6 mainloop; epilogue now writes
// bf16 hi/lo pairs straight into the attention layout).
// ===========================================================================
#define TPITCH 80
#define TILE_B 10240
#define STAGE_B 40960
#define PROJ_SMEM 81920

__global__ void __launch_bounds__(256) proj_mma_kernel(
    const float* __restrict__ bq, const float* __restrict__ bk,
    const float* __restrict__ bv)
{
    extern __shared__ char smc[];
    const uint32_t sb = smem_u32(smc);

    const int tid  = threadIdx.x;
    const int lane = tid & 31;
    const int wid  = tid >> 5;
    const int wm   = wid & 3;
    const int wn   = wid >> 2;
    const int m0   = blockIdx.x * 128;
    const int n0   = blockIdx.y * 128;
    const int which = blockIdx.z;

    const __nv_bfloat16* __restrict__ Bh = g_Whi + which * 262144;
    const __nv_bfloat16* __restrict__ Bl = g_Wlo + which * 262144;
    const float* __restrict__ bias = (which == 0) ? bq : (which == 1) ? bk : bv;
    __nv_bfloat16* __restrict__ outH = (which == 0) ? g_Qh : (which == 1) ? g_Kh : g_Vh;
    __nv_bfloat16* __restrict__ outL = (which == 0) ? g_Ql : (which == 1) ? g_Kl : g_Vl;

    const int r0a = tid >> 2;
    const int ch  = tid & 3;

    float acc[2][8][4];
#pragma unroll
    for (int a = 0; a < 2; a++)
#pragma unroll
        for (int b = 0; b < 8; b++)
#pragma unroll
            for (int c = 0; c < 4; c++) acc[a][b][c] = 0.0f;

    auto issue = [&](int c) {
        const int k0 = c * 32;
        const uint32_t st = sb + (c & 1) * STAGE_B;
#pragma unroll
        for (int i = 0; i < 2; i++) {
            const int row = r0a + i * 64;
            const uint32_t off = row * TPITCH + ch * 16;
            const int ga = (m0 + row) * 512 + k0 + ch * 8;
            const int gb = (n0 + row) * 512 + k0 + ch * 8;
            CP16(st + off,              g_Xhi + ga);
            CP16(st + TILE_B + off,     g_Xlo + ga);
            CP16(st + 2 * TILE_B + off, Bh + gb);
            CP16(st + 3 * TILE_B + off, Bl + gb);
        }
        asm volatile("cp.async.commit_group;");
    };

    issue(0);
    for (int c = 0; c < 16; c++) {
        if (c < 15) {
            issue(c + 1);
            asm volatile("cp.async.wait_group 1;");
        } else {
            asm volatile("cp.async.wait_group 0;");
        }
        __syncthreads();

        const uint32_t st = sb + (c & 1) * STAGE_B;
#pragma unroll
        for (int ks = 0; ks < 2; ks++) {
            uint32_t a_hi[2][4], a_lo[2][4];
            const int al = lane & 15;
            const int ac = ks * 2 + (lane >> 4);
#pragma unroll
            for (int mt = 0; mt < 2; mt++) {
                const uint32_t ad = st + (wm * 32 + mt * 16 + al) * TPITCH + ac * 16;
                LDMX4(a_hi[mt], ad);
                LDMX4(a_lo[mt], ad + TILE_B);
            }
            uint32_t b_hi[8][2], b_lo[8][2];
            const int br = (lane >> 4) * 8 + (lane & 7);
            const int bc = ks * 2 + ((lane >> 3) & 1);
#pragma unroll
            for (int p = 0; p < 4; p++) {
                const uint32_t bd = st + 2 * TILE_B
                                  + (wn * 64 + p * 16 + br) * TPITCH + bc * 16;
                uint32_t r[4];
                LDMX4(r, bd);
                b_hi[2 * p][0] = r[0]; b_hi[2 * p][1] = r[1];
                b_hi[2 * p + 1][0] = r[2]; b_hi[2 * p + 1][1] = r[3];
                LDMX4(r, bd + TILE_B);
                b_lo[2 * p][0] = r[0]; b_lo[2 * p][1] = r[1];
                b_lo[2 * p + 1][0] = r[2]; b_lo[2 * p + 1][1] = r[3];
            }
#pragma unroll
            for (int mt = 0; mt < 2; mt++)
#pragma unroll
                for (int nt = 0; nt < 8; nt++) {
                    mma16816(acc[mt][nt], a_hi[mt], b_hi[nt]);
                    mma16816(acc[mt][nt], a_hi[mt], b_lo[nt]);
                    mma16816(acc[mt][nt], a_lo[mt], b_hi[nt]);
                }
        }
        __syncthreads();
    }

    // ---- epilogue: bias, split hi/lo, scatter into [B][nh][W][H][d] ----
    const int g  = lane >> 2;
    const int tg = lane & 3;
#pragma unroll
    for (int mt = 0; mt < 2; mt++) {
#pragma unroll
        for (int half = 0; half < 2; half++) {
            const int pix = m0 + wm * 32 + mt * 16 + g + half * 8;
            const int b = pix >> 14;
            const int h = (pix >> 7) & 127;
            const int w = pix & 127;
#pragma unroll
            for (int nt = 0; nt < 8; nt++) {
                const int f  = n0 + wn * 64 + nt * 8 + tg * 2;
                const int nh = f >> 6;
                const int dd = f & 63;
                float2 bb = *(const float2*)(bias + f);
                const float ox = acc[mt][nt][half * 2 + 0] + bb.x;
                const float oy = acc[mt][nt][half * 2 + 1] + bb.y;
                __nv_bfloat16 hx = __float2bfloat16(ox);
                __nv_bfloat16 hy = __float2bfloat16(oy);
                __nv_bfloat162 hp; hp.x = hx; hp.y = hy;
                __nv_bfloat162 lp;
                lp.x = __float2bfloat16(ox - __bfloat162float(hx));
                lp.y = __float2bfloat16(oy - __bfloat162float(hy));
                const int off = (((b * 8 + nh) * 128 + w) * 128 + h) * 64 + dd;
                *(__nv_bfloat162*)(outH + off) = hp;
                *(__nv_bfloat162*)(outL + off) = lp;
            }
        }
    }
}

// ===========================================================================
// Tensor-core axial attention.  One CTA per (b, head, line), 256 thr, 8 warps,
// 2 CTAs/SM.  smem 96 KB: Qh 0, Ql 16K, Kh 32K, Kl 48K, Vh 64K, Vl 80K;
// each tile 128 rows x 128 B, SW128-swizzled (conflict-free ldmatrix).
// V stays row-major [seq][d]; O=P*V uses ldmatrix.x4.trans.
// S accums + softmax + P stay in registers.
// ===========================================================================
#define AQHI 0
#define AQLO 16384
#define AKHI 32768
#define AKLO 49152
#define AVHI 65536
#define AVLO 81920
#define ATTN_SMEM 98304

__global__ void __launch_bounds__(256, 2) attn_mma_kernel(float* __restrict__ out, const int stage)
{
    extern __shared__ char sm[];
    const uint32_t sb = smem_u32(sm);

    const int tid  = threadIdx.x;
    const int lane = tid & 31;
    const int wid  = tid >> 5;
    const int x_   = blockIdx.x;
    const int b8n  = blockIdx.z * 8 + blockIdx.y;

    const __nv_bfloat16* __restrict__ Vhp = (stage == 1) ? g_Vh : g_XVh;
    const __nv_bfloat16* __restrict__ Vlp = (stage == 1) ? g_Vl : g_XVl;

    int qbase, rstride;
    if (stage == 1) {
        qbase   = (b8n * 128 + x_) * 8192;
        rstride = 64;
    } else {
        qbase   = b8n * 1048576 + x_ * 64;
        rstride = 8192;
    }
    const int vbase = (b8n * 128 + x_) * 8192;

    // ---- async loads: 6 tiles x 16 KB, SW128-swizzled destinations ----
    for (int idx = tid; idx < 1024; idx += 256) {
        const int row = idx >> 3;
        const int ch  = idx & 7;
        const int qoff = qbase + row * rstride + ch * 8;
        const int voff = vbase + row * 64 + ch * 8;
        const uint32_t dst = ASW(row * 128 + ch * 16);
        CP16(sb + AQHI + dst, g_Qh + qoff);
        CP16(sb + AQLO + dst, g_Ql + qoff);
        CP16(sb + AKHI + dst, g_Kh + qoff);
        CP16(sb + AKLO + dst, g_Kl + qoff);
        CP16(sb + AVHI + dst, Vhp + voff);
        CP16(sb + AVLO + dst, Vlp + voff);
    }
    asm volatile("cp.async.commit_group;");
    asm volatile("cp.async.wait_group 0;");
    __syncthreads();

    // ---- S = Q * K^T  (warp strip m16 x N=128), bf16x3 ----
    float sacc[16][4];
#pragma unroll
    for (int j = 0; j < 16; j++)
#pragma unroll
        for (int c = 0; c < 4; c++) sacc[j][c] = 0.0f;

    const int m0w = wid * 16;
    const int alr = lane & 15;
    const int alc = lane >> 4;
    const int blr = ((lane >> 4) << 3) + (lane & 7);
    const int blc = (lane >> 3) & 1;

#pragma unroll
    for (int kt = 0; kt < 4; kt++) {
        uint32_t ahi[4], alo[4];
        const uint32_t aa = sb + AQHI + ASW((m0w + alr) * 128 + (kt * 2 + alc) * 16);
        LDMX4(ahi, aa);
        LDMX4(alo, aa + (AQLO - AQHI));
#pragma unroll
        for (int p = 0; p < 8; p++) {
            const uint32_t ba = sb + AKHI + ASW((p * 16 + blr) * 128 + (kt * 2 + blc) * 16);
            uint32_t bh[4], bl[4];
            LDMX4(bh, ba);
            LDMX4(bl, ba + (AKLO - AKHI));
            mma16816(sacc[2 * p],     ahi, &bh[0]);
            mma16816(sacc[2 * p],     ahi, &bl[0]);
            mma16816(sacc[2 * p],     alo, &bh[0]);
            mma16816(sacc[2 * p + 1], ahi, &bh[2]);
            mma16816(sacc[2 * p + 1], ahi, &bl[2]);
            mma16816(sacc[2 * p + 1], alo, &bh[2]);
        }
    }

    // ---- clip(+-(1-eps)), /8, softmax per row, clip [eps,1-eps] ----
    {
        const float lo = -1.0f + EPSI, hi = 1.0f - EPSI;
#pragma unroll
        for (int j = 0; j < 16; j++)
#pragma unroll
            for (int c = 0; c < 4; c++)
                sacc[j][c] = fminf(fmaxf(sacc[j][c], lo), hi) * 0.125f;

        float mx0 = -1e30f, mx1 = -1e30f;
#pragma unroll
        for (int j = 0; j < 16; j++) {
            mx0 = fmaxf(mx0, fmaxf(sacc[j][0], sacc[j][1]));
            mx1 = fmaxf(mx1, fmaxf(sacc[j][2], sacc[j][3]));
        }
        mx0 = fmaxf(mx0, __shfl_xor_sync(0xffffffffu, mx0, 1));
        mx0 = fmaxf(mx0, __shfl_xor_sync(0xffffffffu, mx0, 2));
        mx1 = fmaxf(mx1, __shfl_xor_sync(0xffffffffu, mx1, 1));
        mx1 = fmaxf(mx1, __shfl_xor_sync(0xffffffffu, mx1, 2));

        float s0 = 0.0f, s1 = 0.0f;
#pragma unroll
        for (int j = 0; j < 16; j++) {
            sacc[j][0] = __expf(sacc[j][0] - mx0);
            sacc[j][1] = __expf(sacc[j][1] - mx0);
            sacc[j][2] = __expf(sacc[j][2] - mx1);
            sacc[j][3] = __expf(sacc[j][3] - mx1);
            s0 += sacc[j][0] + sacc[j][1];
            s1 += sacc[j][2] + sacc[j][3];
        }
        s0 += __shfl_xor_sync(0xffffffffu, s0, 1);
        s0 += __shfl_xor_sync(0xffffffffu, s0, 2);
        s1 += __shfl_xor_sync(0xffffffffu, s1, 1);
        s1 += __shfl_xor_sync(0xffffffffu, s1, 2);
        const float i0 = 1.0f / s0, i1 = 1.0f / s1;
        const float alo2 = EPSI, ahi2 = 1.0f - EPSI;
#pragma unroll
        for (int j = 0; j < 16; j++) {
            sacc[j][0] = fminf(fmaxf(sacc[j][0] * i0, alo2), ahi2);
            sacc[j][1] = fminf(fmaxf(sacc[j][1] * i0, alo2), ahi2);
            sacc[j][2] = fminf(fmaxf(sacc[j][2] * i1, alo2), ahi2);
            sacc[j][3] = fminf(fmaxf(sacc[j][3] * i1, alo2), ahi2);
        }
    }

    // ---- O = P * V  (m16 x N=64, K=128); V via ldmatrix.trans ----
    float oacc[8][4];
#pragma unroll
    for (int j = 0; j < 8; j++)
#pragma unroll
        for (int c = 0; c < 4; c++) oacc[j][c] = 0.0f;

    // trans-tile row/col for V[seq][d]:
    //   row (seq within k16 group) = (lane&7) + ((lane>>3)&1)*8
    //   col chunk (8 d-values = 16B) = lane>>4
    const int vr = (lane & 7) + ((lane >> 3) & 1) * 8;
    const int vc = lane >> 4;

#pragma unroll
    for (int jj = 0; jj < 8; jj++) {
        const int e = 2 * jj, o = 2 * jj + 1;
        uint32_t phi[4], plo[4];
        {
            float p00 = sacc[e][0], p01 = sacc[e][1];
            float p02 = sacc[e][2], p03 = sacc[e][3];
            float p10 = sacc[o][0], p11 = sacc[o][1];
            float p12 = sacc[o][2], p13 = sacc[o][3];
            __nv_bfloat16 h;
            float r0, r1;
            phi[0] = pack_bf16x2(p00, p01);
            h = __float2bfloat16(p00); r0 = p00 - __bfloat162float(h);
            h = __float2bfloat16(p01); r1 = p01 - __bfloat162float(h);
            plo[0] = pack_bf16x2(r0, r1);
            phi[1] = pack_bf16x2(p02, p03);
            h = __float2bfloat16(p02); r0 = p02 - __bfloat162float(h);
            h = __float2bfloat16(p03); r1 = p03 - __bfloat162float(h);
            plo[1] = pack_bf16x2(r0, r1);
            phi[2] = pack_bf16x2(p10, p11);
            h = __float2bfloat16(p10); r0 = p10 - __bfloat162float(h);
            h = __float2bfloat16(p11); r1 = p11 - __bfloat162float(h);
            plo[2] = pack_bf16x2(r0, r1);
            phi[3] = pack_bf16x2(p12, p13);
            h = __float2bfloat16(p12); r0 = p12 - __bfloat162float(h);
            h = __float2bfloat16(p13); r1 = p13 - __bfloat162float(h);
            plo[3] = pack_bf16x2(r0, r1);
        }
#pragma unroll
        for (int np = 0; np < 4; np++) {
            const uint32_t ba = sb + AVHI
                + ASW((jj * 16 + vr) * 128 + np * 32 + vc * 16);
            uint32_t bh[4], bl[4];
            LDMX4T(bh, ba);
            LDMX4T(bl, ba + (AVLO - AVHI));
            mma16816(oacc[2 * np],     phi, &bh[0]);
            mma16816(oacc[2 * np],     phi, &bl[0]);
            mma16816(oacc[2 * np],     plo, &bh[0]);
            mma16816(oacc[2 * np + 1], phi, &bh[2]);
            mma16816(oacc[2 * np + 1], phi, &bl[2]);
            mma16816(oacc[2 * np + 1], plo, &bh[2]);
        }
    }

    // ---- epilogue ----
    const int g  = lane >> 2;
    const int t4 = lane & 3;
    if (stage == 1) {
        // XV hi/lo [b][n][h][w][d]: row = h, col = d, w = x_
        const int base = b8n * 1048576 + x_ * 64;
#pragma unroll
        for (int nt = 0; nt < 8; nt++) {
            const int d = nt * 8 + t4 * 2;
#pragma unroll
            for (int half = 0; half < 2; half++) {
                const float ox = oacc[nt][half * 2 + 0];
                const float oy = oacc[nt][half * 2 + 1];
                __nv_bfloat16 hx = __float2bfloat16(ox);
                __nv_bfloat16 hy = __float2bfloat16(oy);
                __nv_bfloat162 hp; hp.x = hx; hp.y = hy;
                __nv_bfloat162 lp;
                lp.x = __float2bfloat16(ox - __bfloat162float(hx));
                lp.y = __float2bfloat16(oy - __bfloat162float(hy));
                const int off = base + (m0w + g + half * 8) * 8192 + d;
                *(__nv_bfloat162*)(g_XVh + off) = hp;
                *(__nv_bfloat162*)(g_XVl + off) = lp;
            }
        }
    } else {
        // out[b][h=x_][w=row][c=d*8+n]
        const int n = b8n & 7;
        const int b = b8n >> 3;
        const int base = (b * 128 + x_) * 65536 + n;
#pragma unroll
        for (int nt = 0; nt < 8; nt++) {
            const int d = nt * 8 + t4 * 2;
            out[base + (m0w + g) * 512 + d * 8]           = oacc[nt][0];
            out[base + (m0w + g) * 512 + (d + 1) * 8]     = oacc[nt][1];
            out[base + (m0w + g + 8) * 512 + d * 8]       = oacc[nt][2];
            out[base + (m0w + g + 8) * 512 + (d + 1) * 8] = oacc[nt][3];
        }
    }
}

// ---------------------------------------------------------------------------
extern "C" void kernel_launch(void* const* d_in, const int* in_sizes, int n_in,
                              void* d_out, int out_size)
{
    const float* x  = (const float*)d_in[0];
    const float* wq = (const float*)d_in[1];
    const float* bq = (const float*)d_in[2];
    const float* wk = (const float*)d_in[3];
    const float* bk = (const float*)d_in[4];
    const float* wv = (const float*)d_in[5];
    const float* bv = (const float*)d_in[6];
    float* out = (float*)d_out;

    cudaFuncSetAttribute((const void*)attn_mma_kernel,
                         cudaFuncAttributeMaxDynamicSharedMemorySize, ATTN_SMEM);
    cudaFuncSetAttribute((const void*)proj_mma_kernel,
                         cudaFuncAttributeMaxDynamicSharedMemorySize, PROJ_SMEM);

    xsplit_kernel<<<32768, 256>>>(x);
    wsplit_kernel<<<3072, 256>>>(wq, wk, wv);

    dim3 pg(512, 4, 3);
    proj_mma_kernel<<<pg, 256, PROJ_SMEM>>>(bq, bk, bv);

    dim3 ag(128, 8, 4);
    attn_mma_kernel<<<ag, 256, ATTN_SMEM>>>(out, 1);
    attn_mma_kernel<<<ag, 256, ATTN_SMEM>>>(out, 2);
}

// round 9
// speedup vs baseline: 3.1793x; 1.1336x over previous
#include <cuda_runtime.h>
#include <cuda_bf16.h>
#include <cstdint>

#define EPSI 1e-7f

// ===========================================================================
// Scratch (__device__ globals; no allocation allowed).
// Qh/Ql,Kh/Kl,Vh/Vl: bf16 hi/lo, [B][nh][W][H][d].
// XVh/XVl: bf16 hi/lo, [B][nh][H][W][d].
// Xhi/Xlo: bf16 split of x, [pix][c].  Whi/Wlo: bf16 split of W^T, [p][f][c].
// ===========================================================================
__device__ __nv_bfloat16 g_Qh[33554432];
__device__ __nv_bfloat16 g_Ql[33554432];
__device__ __nv_bfloat16 g_Kh[33554432];
__device__ __nv_bfloat16 g_Kl[33554432];
__device__ __nv_bfloat16 g_Vh[33554432];
__device__ __nv_bfloat16 g_Vl[33554432];
__device__ __nv_bfloat16 g_XVh[33554432];
__device__ __nv_bfloat16 g_XVl[33554432];
__device__ __nv_bfloat16 g_Xhi[33554432];
__device__ __nv_bfloat16 g_Xlo[33554432];
__device__ __nv_bfloat16 g_Whi[786432];
__device__ __nv_bfloat16 g_Wlo[786432];

// ===========================================================================
// Helpers (sm_80-era tensor path; compiles on plain compute_103 target)
// ===========================================================================
__device__ __forceinline__ uint32_t smem_u32(const void* p) {
    uint32_t a;
    asm("{ .reg .u64 t; cvta.to.shared.u64 t, %1; cvt.u32.u64 %0, t; }"
        : "=r"(a) : "l"(p));
    return a;
}

#define LDMX4(r, addr) \
    asm volatile("ldmatrix.sync.aligned.m8n8.x4.shared.b16 {%0,%1,%2,%3}, [%4];" \
        : "=r"((r)[0]), "=r"((r)[1]), "=r"((r)[2]), "=r"((r)[3]) : "r"(addr))

#define LDMX4T(r, addr) \
    asm volatile("ldmatrix.sync.aligned.m8n8.x4.trans.shared.b16 {%0,%1,%2,%3}, [%4];" \
        : "=r"((r)[0]), "=r"((r)[1]), "=r"((r)[2]), "=r"((r)[3]) : "r"(addr))

__device__ __forceinline__ void mma16816(float* d, const uint32_t* a, const uint32_t* b) {
    asm volatile(
        "mma.sync.aligned.m16n8k16.row.col.f32.bf16.bf16.f32 "
        "{%0,%1,%2,%3}, {%4,%5,%6,%7}, {%8,%9}, {%0,%1,%2,%3};"
        : "+f"(d[0]), "+f"(d[1]), "+f"(d[2]), "+f"(d[3])
        : "r"(a[0]), "r"(a[1]), "r"(a[2]), "r"(a[3]), "r"(b[0]), "r"(b[1]));
}

#define CP16(dst, src) \
    asm volatile("cp.async.cg.shared.global [%0], [%1], 16;" \
        :: "r"(dst), "l"((const void*)(src)))

__device__ __forceinline__ uint32_t pack_bf16x2(float f0, float f1) {
    __nv_bfloat162 t = __floats2bfloat162_rn(f0, f1);   // x = f0 (low half)
    return *reinterpret_cast<uint32_t*>(&t);
}

// SW128 swizzle on byte offsets (rows are 128 B)
#define ASW(off) ((uint32_t)(off) ^ ((((uint32_t)(off)) >> 3) & 0x70u))

// ===========================================================================
// x -> bf16 hi/lo split
// ===========================================================================
__global__ void __launch_bounds__(256) xsplit_kernel(const float* __restrict__ x)
{
    const int i = blockIdx.x * 256 + threadIdx.x;
    float4 v = ((const float4*)x)[i];
    __nv_bfloat16 h0 = __float2bfloat16(v.x);
    __nv_bfloat16 h1 = __float2bfloat16(v.y);
    __nv_bfloat16 h2 = __float2bfloat16(v.z);
    __nv_bfloat16 h3 = __float2bfloat16(v.w);
    __nv_bfloat162 hp0; hp0.x = h0; hp0.y = h1;
    __nv_bfloat162 hp1; hp1.x = h2; hp1.y = h3;
    __nv_bfloat162 lp0;
    lp0.x = __float2bfloat16(v.x - __bfloat162float(h0));
    lp0.y = __float2bfloat16(v.y - __bfloat162float(h1));
    __nv_bfloat162 lp1;
    lp1.x = __float2bfloat16(v.z - __bfloat162float(h2));
    lp1.y = __float2bfloat16(v.w - __bfloat162float(h3));
    ((__nv_bfloat162*)g_Xhi)[i * 2 + 0] = hp0;
    ((__nv_bfloat162*)g_Xhi)[i * 2 + 1] = hp1;
    ((__nv_bfloat162*)g_Xlo)[i * 2 + 0] = lp0;
    ((__nv_bfloat162*)g_Xlo)[i * 2 + 1] = lp1;
}

// ===========================================================================
// W -> transposed bf16 hi/lo split: WT[p][f][c] = W_p[c][f]
// ===========================================================================
__global__ void __launch_bounds__(256) wsplit_kernel(
    const float* __restrict__ wq, const float* __restrict__ wk,
    const float* __restrict__ wv)
{
    const int idx = blockIdx.x * 256 + threadIdx.x;
    const int p = idx >> 18;
    const int f = (idx >> 9) & 511;
    const int c = idx & 511;
    const float* __restrict__ W = (p == 0) ? wq : (p == 1) ? wk : wv;
    const float v = W[c * 512 + f];
    __nv_bfloat16 h = __float2bfloat16(v);
    g_Whi[idx] = h;
    g_Wlo[idx] = __float2bfloat16(v - __bfloat162float(h));
}

// ===========================================================================
// Projection via warp-level mma.sync.  B fragments consumed immediately
// (low register pressure) + forced 2 CTAs/SM.
// ===========================================================================
#define TPITCH 80
#define TILE_B 10240
#define STAGE_B 40960
#define PROJ_SMEM 81920

__global__ void __launch_bounds__(256, 2) proj_mma_kernel(
    const float* __restrict__ bq, const float* __restrict__ bk,
    const float* __restrict__ bv)
{
    extern __shared__ char smc[];
    const uint32_t sb = smem_u32(smc);

    const int tid  = threadIdx.x;
    const int lane = tid & 31;
    const int wid  = tid >> 5;
    const int wm   = wid & 3;
    const int wn   = wid >> 2;
    const int m0   = blockIdx.x * 128;
    const int n0   = blockIdx.y * 128;
    const int which = blockIdx.z;

    const __nv_bfloat16* __restrict__ Bh = g_Whi + which * 262144;
    const __nv_bfloat16* __restrict__ Bl = g_Wlo + which * 262144;
    const float* __restrict__ bias = (which == 0) ? bq : (which == 1) ? bk : bv;
    __nv_bfloat16* __restrict__ outH = (which == 0) ? g_Qh : (which == 1) ? g_Kh : g_Vh;
    __nv_bfloat16* __restrict__ outL = (which == 0) ? g_Ql : (which == 1) ? g_Kl : g_Vl;

    const int r0a = tid >> 2;
    const int ch  = tid & 3;

    float acc[2][8][4];
#pragma unroll
    for (int a = 0; a < 2; a++)
#pragma unroll
        for (int b = 0; b < 8; b++)
#pragma unroll
            for (int c = 0; c < 4; c++) acc[a][b][c] = 0.0f;

    auto issue = [&](int c) {
        const int k0 = c * 32;
        const uint32_t st = sb + (c & 1) * STAGE_B;
#pragma unroll
        for (int i = 0; i < 2; i++) {
            const int row = r0a + i * 64;
            const uint32_t off = row * TPITCH + ch * 16;
            const int ga = (m0 + row) * 512 + k0 + ch * 8;
            const int gb = (n0 + row) * 512 + k0 + ch * 8;
            CP16(st + off,              g_Xhi + ga);
            CP16(st + TILE_B + off,     g_Xlo + ga);
            CP16(st + 2 * TILE_B + off, Bh + gb);
            CP16(st + 3 * TILE_B + off, Bl + gb);
        }
        asm volatile("cp.async.commit_group;");
    };

    issue(0);
    for (int c = 0; c < 16; c++) {
        if (c < 15) {
            issue(c + 1);
            asm volatile("cp.async.wait_group 1;");
        } else {
            asm volatile("cp.async.wait_group 0;");
        }
        __syncthreads();

        const uint32_t st = sb + (c & 1) * STAGE_B;
#pragma unroll
        for (int ks = 0; ks < 2; ks++) {
            uint32_t a_hi[2][4], a_lo[2][4];
            const int al = lane & 15;
            const int ac = ks * 2 + (lane >> 4);
#pragma unroll
            for (int mt = 0; mt < 2; mt++) {
                const uint32_t ad = st + (wm * 32 + mt * 16 + al) * TPITCH + ac * 16;
                LDMX4(a_hi[mt], ad);
                LDMX4(a_lo[mt], ad + TILE_B);
            }
            const int br = (lane >> 4) * 8 + (lane & 7);
            const int bc = ks * 2 + ((lane >> 3) & 1);
            // B fragments loaded and consumed immediately (8 live regs)
#pragma unroll
            for (int p = 0; p < 4; p++) {
                const uint32_t bd = st + 2 * TILE_B
                                  + (wn * 64 + p * 16 + br) * TPITCH + bc * 16;
                uint32_t bh[4], bl[4];
                LDMX4(bh, bd);
                LDMX4(bl, bd + TILE_B);
#pragma unroll
                for (int mt = 0; mt < 2; mt++) {
                    mma16816(acc[mt][2 * p],     a_hi[mt], &bh[0]);
                    mma16816(acc[mt][2 * p],     a_hi[mt], &bl[0]);
                    mma16816(acc[mt][2 * p],     a_lo[mt], &bh[0]);
                    mma16816(acc[mt][2 * p + 1], a_hi[mt], &bh[2]);
                    mma16816(acc[mt][2 * p + 1], a_hi[mt], &bl[2]);
                    mma16816(acc[mt][2 * p + 1], a_lo[mt], &bh[2]);
                }
            }
        }
        __syncthreads();
    }

    // ---- epilogue: bias, split hi/lo, scatter into [B][nh][W][H][d] ----
    const int g  = lane >> 2;
    const int tg = lane & 3;
#pragma unroll
    for (int mt = 0; mt < 2; mt++) {
#pragma unroll
        for (int half = 0; half < 2; half++) {
            const int pix = m0 + wm * 32 + mt * 16 + g + half * 8;
            const int b = pix >> 14;
            const int h = (pix >> 7) & 127;
            const int w = pix & 127;
#pragma unroll
            for (int nt = 0; nt < 8; nt++) {
                const int f  = n0 + wn * 64 + nt * 8 + tg * 2;
                const int nh = f >> 6;
                const int dd = f & 63;
                float2 bb = *(const float2*)(bias + f);
                const float ox = acc[mt][nt][half * 2 + 0] + bb.x;
                const float oy = acc[mt][nt][half * 2 + 1] + bb.y;
                __nv_bfloat16 hx = __float2bfloat16(ox);
                __nv_bfloat16 hy = __float2bfloat16(oy);
                __nv_bfloat162 hp; hp.x = hx; hp.y = hy;
                __nv_bfloat162 lp;
                lp.x = __float2bfloat16(ox - __bfloat162float(hx));
                lp.y = __float2bfloat16(oy - __bfloat162float(hy));
                const int off = (((b * 8 + nh) * 128 + w) * 128 + h) * 64 + dd;
                *(__nv_bfloat162*)(outH + off) = hp;
                *(__nv_bfloat162*)(outL + off) = lp;
            }
        }
    }
}

// ===========================================================================
// Tensor-core axial attention (R8 structure + split-group async prologue).
// smem 96 KB: Qh 0, Ql 16K, Kh 32K, Kl 48K, Vh 64K, Vl 80K; SW128-swizzled.
// ===========================================================================
#define AQHI 0
#define AQLO 16384
#define AKHI 32768
#define AKLO 49152
#define AVHI 65536
#define AVLO 81920
#define ATTN_SMEM 98304

__global__ void __launch_bounds__(256, 2) attn_mma_kernel(float* __restrict__ out, const int stage)
{
    extern __shared__ char sm[];
    const uint32_t sb = smem_u32(sm);

    const int tid  = threadIdx.x;
    const int lane = tid & 31;
    const int wid  = tid >> 5;
    const int x_   = blockIdx.x;
    const int b8n  = blockIdx.z * 8 + blockIdx.y;

    const __nv_bfloat16* __restrict__ Vhp = (stage == 1) ? g_Vh : g_XVh;
    const __nv_bfloat16* __restrict__ Vlp = (stage == 1) ? g_Vl : g_XVl;

    int qbase, rstride;
    if (stage == 1) {
        qbase   = (b8n * 128 + x_) * 8192;
        rstride = 64;
    } else {
        qbase   = b8n * 1048576 + x_ * 64;
        rstride = 8192;
    }
    const int vbase = (b8n * 128 + x_) * 8192;

    // ---- group 0: Q,K tiles (needed for S) ----
    for (int idx = tid; idx < 1024; idx += 256) {
        const int row = idx >> 3;
        const int ch  = idx & 7;
        const int qoff = qbase + row * rstride + ch * 8;
        const uint32_t dst = ASW(row * 128 + ch * 16);
        CP16(sb + AQHI + dst, g_Qh + qoff);
        CP16(sb + AQLO + dst, g_Ql + qoff);
        CP16(sb + AKHI + dst, g_Kh + qoff);
        CP16(sb + AKLO + dst, g_Kl + qoff);
    }
    asm volatile("cp.async.commit_group;");
    // ---- group 1: V tiles (needed only for O) ----
    for (int idx = tid; idx < 1024; idx += 256) {
        const int row = idx >> 3;
        const int ch  = idx & 7;
        const int voff = vbase + row * 64 + ch * 8;
        const uint32_t dst = ASW(row * 128 + ch * 16);
        CP16(sb + AVHI + dst, Vhp + voff);
        CP16(sb + AVLO + dst, Vlp + voff);
    }
    asm volatile("cp.async.commit_group;");

    asm volatile("cp.async.wait_group 1;");   // Q,K ready; V may still fly
    __syncthreads();

    // ---- S = Q * K^T  (warp strip m16 x N=128), bf16x3 ----
    float sacc[16][4];
#pragma unroll
    for (int j = 0; j < 16; j++)
#pragma unroll
        for (int c = 0; c < 4; c++) sacc[j][c] = 0.0f;

    const int m0w = wid * 16;
    const int alr = lane & 15;
    const int alc = lane >> 4;
    const int blr = ((lane >> 4) << 3) + (lane & 7);
    const int blc = (lane >> 3) & 1;

#pragma unroll
    for (int kt = 0; kt < 4; kt++) {
        uint32_t ahi[4], alo[4];
        const uint32_t aa = sb + AQHI + ASW((m0w + alr) * 128 + (kt * 2 + alc) * 16);
        LDMX4(ahi, aa);
        LDMX4(alo, aa + (AQLO - AQHI));
#pragma unroll
        for (int p = 0; p < 8; p++) {
            const uint32_t ba = sb + AKHI + ASW((p * 16 + blr) * 128 + (kt * 2 + blc) * 16);
            uint32_t bh[4], bl[4];
            LDMX4(bh, ba);
            LDMX4(bl, ba + (AKLO - AKHI));
            mma16816(sacc[2 * p],     ahi, &bh[0]);
            mma16816(sacc[2 * p],     ahi, &bl[0]);
            mma16816(sacc[2 * p],     alo, &bh[0]);
            mma16816(sacc[2 * p + 1], ahi, &bh[2]);
            mma16816(sacc[2 * p + 1], ahi, &bl[2]);
            mma16816(sacc[2 * p + 1], alo, &bh[2]);
        }
    }

    // ---- clip(+-(1-eps)), /8, softmax per row, clip [eps,1-eps] ----
    {
        const float lo = -1.0f + EPSI, hi = 1.0f - EPSI;
#pragma unroll
        for (int j = 0; j < 16; j++)
#pragma unroll
            for (int c = 0; c < 4; c++)
                sacc[j][c] = fminf(fmaxf(sacc[j][c], lo), hi) * 0.125f;

        float mx0 = -1e30f, mx1 = -1e30f;
#pragma unroll
        for (int j = 0; j < 16; j++) {
            mx0 = fmaxf(mx0, fmaxf(sacc[j][0], sacc[j][1]));
            mx1 = fmaxf(mx1, fmaxf(sacc[j][2], sacc[j][3]));
        }
        mx0 = fmaxf(mx0, __shfl_xor_sync(0xffffffffu, mx0, 1));
        mx0 = fmaxf(mx0, __shfl_xor_sync(0xffffffffu, mx0, 2));
        mx1 = fmaxf(mx1, __shfl_xor_sync(0xffffffffu, mx1, 1));
        mx1 = fmaxf(mx1, __shfl_xor_sync(0xffffffffu, mx1, 2));

        float s0 = 0.0f, s1 = 0.0f;
#pragma unroll
        for (int j = 0; j < 16; j++) {
            sacc[j][0] = __expf(sacc[j][0] - mx0);
            sacc[j][1] = __expf(sacc[j][1] - mx0);
            sacc[j][2] = __expf(sacc[j][2] - mx1);
            sacc[j][3] = __expf(sacc[j][3] - mx1);
            s0 += sacc[j][0] + sacc[j][1];
            s1 += sacc[j][2] + sacc[j][3];
        }
        s0 += __shfl_xor_sync(0xffffffffu, s0, 1);
        s0 += __shfl_xor_sync(0xffffffffu, s0, 2);
        s1 += __shfl_xor_sync(0xffffffffu, s1, 1);
        s1 += __shfl_xor_sync(0xffffffffu, s1, 2);
        const float i0 = 1.0f / s0, i1 = 1.0f / s1;
        const float alo2 = EPSI, ahi2 = 1.0f - EPSI;
#pragma unroll
        for (int j = 0; j < 16; j++) {
            sacc[j][0] = fminf(fmaxf(sacc[j][0] * i0, alo2), ahi2);
            sacc[j][1] = fminf(fmaxf(sacc[j][1] * i0, alo2), ahi2);
            sacc[j][2] = fminf(fmaxf(sacc[j][2] * i1, alo2), ahi2);
            sacc[j][3] = fminf(fmaxf(sacc[j][3] * i1, alo2), ahi2);
        }
    }

    asm volatile("cp.async.wait_group 0;");   // V ready
    __syncthreads();

    // ---- O = P * V  (m16 x N=64, K=128); V via ldmatrix.trans ----
    float oacc[8][4];
#pragma unroll
    for (int j = 0; j < 8; j++)
#pragma unroll
        for (int c = 0; c < 4; c++) oacc[j][c] = 0.0f;

    const int vr = (lane & 7) + ((lane >> 3) & 1) * 8;
    const int vc = lane >> 4;

#pragma unroll
    for (int jj = 0; jj < 8; jj++) {
        const int e = 2 * jj, o = 2 * jj + 1;
        uint32_t phi[4], plo[4];
        {
            float p00 = sacc[e][0], p01 = sacc[e][1];
            float p02 = sacc[e][2], p03 = sacc[e][3];
            float p10 = sacc[o][0], p11 = sacc[o][1];
            float p12 = sacc[o][2], p13 = sacc[o][3];
            __nv_bfloat16 h;
            float r0, r1;
            phi[0] = pack_bf16x2(p00, p01);
            h = __float2bfloat16(p00); r0 = p00 - __bfloat162float(h);
            h = __float2bfloat16(p01); r1 = p01 - __bfloat162float(h);
            plo[0] = pack_bf16x2(r0, r1);
            phi[1] = pack_bf16x2(p02, p03);
            h = __float2bfloat16(p02); r0 = p02 - __bfloat162float(h);
            h = __float2bfloat16(p03); r1 = p03 - __bfloat162float(h);
            plo[1] = pack_bf16x2(r0, r1);
            phi[2] = pack_bf16x2(p10, p11);
            h = __float2bfloat16(p10); r0 = p10 - __bfloat162float(h);
            h = __float2bfloat16(p11); r1 = p11 - __bfloat162float(h);
            plo[2] = pack_bf16x2(r0, r1);
            phi[3] = pack_bf16x2(p12, p13);
            h = __float2bfloat16(p12); r0 = p12 - __bfloat162float(h);
            h = __float2bfloat16(p13); r1 = p13 - __bfloat162float(h);
            plo[3] = pack_bf16x2(r0, r1);
        }
#pragma unroll
        for (int np = 0; np < 4; np++) {
            const uint32_t ba = sb + AVHI
                + ASW((jj * 16 + vr) * 128 + np * 32 + vc * 16);
            uint32_t bh[4], bl[4];
            LDMX4T(bh, ba);
            LDMX4T(bl, ba + (AVLO - AVHI));
            mma16816(oacc[2 * np],     phi, &bh[0]);
            mma16816(oacc[2 * np],     phi, &bl[0]);
            mma16816(oacc[2 * np],     plo, &bh[0]);
            mma16816(oacc[2 * np + 1], phi, &bh[2]);
            mma16816(oacc[2 * np + 1], phi, &bl[2]);
            mma16816(oacc[2 * np + 1], plo, &bh[2]);
        }
    }

    // ---- epilogue ----
    const int g  = lane >> 2;
    const int t4 = lane & 3;
    if (stage == 1) {
        const int base = b8n * 1048576 + x_ * 64;
#pragma unroll
        for (int nt = 0; nt < 8; nt++) {
            const int d = nt * 8 + t4 * 2;
#pragma unroll
            for (int half = 0; half < 2; half++) {
                const float ox = oacc[nt][half * 2 + 0];
                const float oy = oacc[nt][half * 2 + 1];
                __nv_bfloat16 hx = __float2bfloat16(ox);
                __nv_bfloat16 hy = __float2bfloat16(oy);
                __nv_bfloat162 hp; hp.x = hx; hp.y = hy;
                __nv_bfloat162 lp;
                lp.x = __float2bfloat16(ox - __bfloat162float(hx));
                lp.y = __float2bfloat16(oy - __bfloat162float(hy));
                const int off = base + (m0w + g + half * 8) * 8192 + d;
                *(__nv_bfloat162*)(g_XVh + off) = hp;
                *(__nv_bfloat162*)(g_XVl + off) = lp;
            }
        }
    } else {
        const int n = b8n & 7;
        const int b = b8n >> 3;
        const int base = (b * 128 + x_) * 65536 + n;
#pragma unroll
        for (int nt = 0; nt < 8; nt++) {
            const int d = nt * 8 + t4 * 2;
            out[base + (m0w + g) * 512 + d * 8]           = oacc[nt][0];
            out[base + (m0w + g) * 512 + (d + 1) * 8]     = oacc[nt][1];
            out[base + (m0w + g + 8) * 512 + d * 8]       = oacc[nt][2];
            out[base + (m0w + g + 8) * 512 + (d + 1) * 8] = oacc[nt][3];
        }
    }
}

// ---------------------------------------------------------------------------
extern "C" void kernel_launch(void* const* d_in, const int* in_sizes, int n_in,
                              void* d_out, int out_size)
{
    const float* x  = (const float*)d_in[0];
    const float* wq = (const float*)d_in[1];
    const float* bq = (const float*)d_in[2];
    const float* wk = (const float*)d_in[3];
    const float* bk = (const float*)d_in[4];
    const float* wv = (const float*)d_in[5];
    const float* bv = (const float*)d_in[6];
    float* out = (float*)d_out;

    cudaFuncSetAttribute((const void*)attn_mma_kernel,
                         cudaFuncAttributeMaxDynamicSharedMemorySize, ATTN_SMEM);
    cudaFuncSetAttribute((const void*)proj_mma_kernel,
                         cudaFuncAttributeMaxDynamicSharedMemorySize, PROJ_SMEM);

    xsplit_kernel<<<32768, 256>>>(x);
    wsplit_kernel<<<3072, 256>>>(wq, wk, wv);

    dim3 pg(512, 4, 3);
    proj_mma_kernel<<<pg, 256, PROJ_SMEM>>>(bq, bk, bv);

    dim3 ag(128, 8, 4);
    attn_mma_kernel<<<ag, 256, ATTN_SMEM>>>(out, 1);
    attn_mma_kernel<<<ag, 256, ATTN_SMEM>>>(out, 2);
}